// round 1
// baseline (speedup 1.0000x reference)
#include <cuda_runtime.h>
#include <math.h>

// Problem constants
static constexpr int B_ = 8;
static constexpr int L_ = 1024;
static constexpr int KE = 1024;   // eigvecs
static constexpr int D_ = 128;
static constexpr int S_ = 16;

// ---------------- scratch (device globals; no allocation allowed) ----------
__device__ float g_rinv[B_ * L_];                 // 32 KB
__device__ float g_h[(long)B_ * L_ * 2 * D_];     // 8 MB
__device__ float g_u[(long)B_ * L_ * D_];         // 4 MB  (u * rinv)
__device__ float g_G[(long)B_ * KE * D_];         // 4 MB  (QTX then G)
__device__ float g_v[(long)B_ * L_ * D_];         // 4 MB  (silu(yssm))
__device__ float g_ar[D_ * S_];
__device__ float g_ai[D_ * S_];
__device__ float g_bc[D_ * S_];
__device__ float g_bns[D_];
__device__ float g_bnb[D_];

// ---------------- prep: SSM tables + batchnorm fold -------------------------
__global__ void k_prep(const float* __restrict__ gamma, const float* __restrict__ beta,
                       const float* __restrict__ mean,  const float* __restrict__ var,
                       const float* __restrict__ log_Delta,
                       const float* __restrict__ Bp,    const float* __restrict__ Cp,
                       const float* __restrict__ log_A_real,
                       const float* __restrict__ A_imag)
{
    int idx = blockIdx.x * blockDim.x + threadIdx.x;
    if (idx < D_ * S_) {
        int d = idx / S_;
        float delta = expf(log_Delta[d]);
        float aRe = -expf(log_A_real[idx]);
        float aIm = A_imag[idx];
        float mag = expf(-1e-3f + delta * aRe);
        float sn, cs;
        sincosf(delta * aIm, &sn, &cs);
        g_ar[idx] = mag * cs;
        g_ai[idx] = mag * sn;
        g_bc[idx] = delta * Bp[idx] * Cp[idx];   // Bbar * Cp
    } else if (idx < D_ * S_ + D_) {
        int d = idx - D_ * S_;
        float sc = gamma[d] * rsqrtf(var[d] + 1e-5f);
        g_bns[d] = sc;
        g_bnb[d] = beta[d] - mean[d] * sc;
    }
}

// ---------------- row inverse-norms of EigVecs ------------------------------
__global__ void k_rinv(const float* __restrict__ E)
{
    int row = blockIdx.x * 8 + (threadIdx.x >> 5);
    int lane = threadIdx.x & 31;
    const float* p = E + (long)row * KE;
    float s = 0.f;
#pragma unroll
    for (int i = 0; i < KE / 32; i++) {
        float v = p[lane + 32 * i];
        s += v * v;
    }
#pragma unroll
    for (int o = 16; o; o >>= 1) s += __shfl_xor_sync(0xffffffffu, s, o);
    if (lane == 0) g_rinv[row] = (s > 0.f) ? (1.0f / sqrtf(s)) : 0.f;
}

// ---------------- gated activation: u' = x1*silu(z)*rinv --------------------
__global__ void k_act()
{
    long idx = (long)blockIdx.x * 256 + threadIdx.x;  // over B*L*D
    int m = (int)(idx >> 7);
    int d = (int)(idx & 127);
    float x1 = g_h[(long)m * 256 + d];
    float z  = g_h[(long)m * 256 + 128 + d];
    float u  = x1 * (z / (1.f + expf(-z)));
    g_u[idx] = u * g_rinv[m];
}

// ---------------- SSM weight: G = QTX * W(b,k,d) ----------------------------
__global__ void k_w(const float* __restrict__ EigVals)
{
    int blk = blockIdx.x;               // B * (KE/64)
    int b  = blk >> 4;
    int k0 = (blk & 15) << 6;
    int d  = threadIdx.x;               // 128
    float lar[S_], lai[S_], lbc[S_];
#pragma unroll
    for (int s = 0; s < S_; s++) {
        lar[s] = g_ar[d * S_ + s];
        lai[s] = g_ai[d * S_ + s];
        lbc[s] = g_bc[d * S_ + s];
    }
#pragma unroll 4
    for (int kk = 0; kk < 64; kk++) {
        int k = k0 + kk;
        float e = 1.0f - __ldg(&EigVals[b * KE + k]);
        float acc = 0.f;
#pragma unroll
        for (int s = 0; s < S_; s++) {
            float x = e * lar[s];
            float y = e * lai[s];
            float omx = 1.f - x;
            float num = x * omx - y * y;         // Re(lamA * conj(1-lamA))
            float den = omx * omx + y * y;       // |1-lamA|^2
            acc += __fdividef(num, den) * lbc[s];
        }
        long gi = ((long)(b * KE + k)) * D_ + d;
        g_G[gi] *= acc;
    }
}

// ---------------- generic 64x64x16 SGEMM ------------------------------------
// C[M,N] = A ? B  ;  TRANSA=false: A is [M,Kc] (lda), TRANSA=true: A is [Kc,M]
// B is [Kc,N] (ldb). All tile dims assumed to divide exactly.
enum { EPI_NONE = 0, EPI_BIAS = 1, EPI_SILU = 2 };

template <bool TRANSA, int EPI, bool BNA>
__global__ __launch_bounds__(256)
void gemm64(const float* __restrict__ A, const float* __restrict__ Bm,
            float* __restrict__ C,
            int Kc, int lda, int ldb, int ldc,
            long sA, long sB, long sC,
            const float* __restrict__ bias,
            const float* __restrict__ rowscale, int rsStride)
{
    A  += (long)blockIdx.z * sA;
    Bm += (long)blockIdx.z * sB;
    C  += (long)blockIdx.z * sC;
    const int m0 = blockIdx.x * 64;
    const int n0 = blockIdx.y * 64;

    __shared__ float As[16][68];   // [contraction][m], padded
    __shared__ float Bs[16][64];   // [contraction][n]

    const int tid = threadIdx.x;
    const int tr = (tid >> 4) << 2;   // row offset within tile (0..60)
    const int tc = (tid & 15) << 2;   // col offset within tile (0..60)

    float acc[4][4] = {};

    for (int p0 = 0; p0 < Kc; p0 += 16) {
        if (TRANSA) {
            int r = tid >> 4;                 // contraction row 0..15
            int c = (tid & 15) << 2;          // m col
            float4 av = *(const float4*)(A + (long)(p0 + r) * lda + m0 + c);
            *(float4*)&As[r][c] = av;
        } else {
            int r = tid >> 2;                 // m row 0..63
            int c = (tid & 3) << 2;           // contraction col
            float4 av = *(const float4*)(A + (long)(m0 + r) * lda + p0 + c);
            if (BNA) {
                av.x = av.x * g_bns[p0 + c + 0] + g_bnb[p0 + c + 0];
                av.y = av.y * g_bns[p0 + c + 1] + g_bnb[p0 + c + 1];
                av.z = av.z * g_bns[p0 + c + 2] + g_bnb[p0 + c + 2];
                av.w = av.w * g_bns[p0 + c + 3] + g_bnb[p0 + c + 3];
            }
            As[c + 0][r] = av.x;
            As[c + 1][r] = av.y;
            As[c + 2][r] = av.z;
            As[c + 3][r] = av.w;
        }
        {
            int r = tid >> 4;
            int c = (tid & 15) << 2;
            *(float4*)&Bs[r][c] = *(const float4*)(Bm + (long)(p0 + r) * ldb + n0 + c);
        }
        __syncthreads();
#pragma unroll
        for (int kk = 0; kk < 16; kk++) {
            float af[4], bf[4];
            *(float4*)af = *(const float4*)&As[kk][tr];
            *(float4*)bf = *(const float4*)&Bs[kk][tc];
#pragma unroll
            for (int i = 0; i < 4; i++)
#pragma unroll
                for (int j = 0; j < 4; j++)
                    acc[i][j] += af[i] * bf[j];
        }
        __syncthreads();
    }

#pragma unroll
    for (int i = 0; i < 4; i++) {
        int row = m0 + tr + i;
        float rs = 1.f;
        if (EPI == EPI_SILU) rs = rowscale[blockIdx.z * rsStride + row];
        float4 o;
        float v;
        v = acc[i][0];
        if (EPI == EPI_BIAS) v += bias[n0 + tc + 0];
        if (EPI == EPI_SILU) { v *= rs; v = v / (1.f + expf(-v)); }
        o.x = v;
        v = acc[i][1];
        if (EPI == EPI_BIAS) v += bias[n0 + tc + 1];
        if (EPI == EPI_SILU) { v *= rs; v = v / (1.f + expf(-v)); }
        o.y = v;
        v = acc[i][2];
        if (EPI == EPI_BIAS) v += bias[n0 + tc + 2];
        if (EPI == EPI_SILU) { v *= rs; v = v / (1.f + expf(-v)); }
        o.z = v;
        v = acc[i][3];
        if (EPI == EPI_BIAS) v += bias[n0 + tc + 3];
        if (EPI == EPI_SILU) { v *= rs; v = v / (1.f + expf(-v)); }
        o.w = v;
        *(float4*)(C + (long)row * ldc + n0 + tc) = o;
    }
}

// ---------------- launch ----------------------------------------------------
extern "C" void kernel_launch(void* const* d_in, const int* in_sizes, int n_in,
                              void* d_out, int out_size)
{
    const float* x        = (const float*)d_in[0];
    // d_in[1] = attn_mask (all true, unused by reference)
    const float* EigVecs  = (const float*)d_in[2];
    const float* EigVals  = (const float*)d_in[3];
    const float* bn_gamma = (const float*)d_in[4];
    const float* bn_beta  = (const float*)d_in[5];
    const float* bn_mean  = (const float*)d_in[6];
    const float* bn_var   = (const float*)d_in[7];
    const float* W_in     = (const float*)d_in[8];
    const float* b_in     = (const float*)d_in[9];
    const float* log_Delta= (const float*)d_in[10];
    const float* Bp       = (const float*)d_in[11];
    const float* Cp       = (const float*)d_in[12];
    const float* log_A    = (const float*)d_in[13];
    const float* A_imag   = (const float*)d_in[14];
    const float* W_out    = (const float*)d_in[15];
    const float* b_out    = (const float*)d_in[16];
    float* y = (float*)d_out;

    float *p_h, *p_u, *p_G, *p_v, *p_rinv;
    cudaGetSymbolAddress((void**)&p_h, g_h);
    cudaGetSymbolAddress((void**)&p_u, g_u);
    cudaGetSymbolAddress((void**)&p_G, g_G);
    cudaGetSymbolAddress((void**)&p_v, g_v);
    cudaGetSymbolAddress((void**)&p_rinv, g_rinv);

    // 1) tables
    k_prep<<<(D_ * S_ + D_ + 255) / 256, 256>>>(bn_gamma, bn_beta, bn_mean, bn_var,
                                                log_Delta, Bp, Cp, log_A, A_imag);
    // 2) row norms
    k_rinv<<<B_ * L_ / 8, 256>>>(EigVecs);
    // 3) in-proj: h = bn(x) @ W_in + b_in   (M=8192, N=256, K=128)
    gemm64<false, EPI_BIAS, true><<<dim3(B_ * L_ / 64, 256 / 64, 1), 256>>>(
        x, W_in, p_h, D_, D_, 2 * D_, 2 * D_, 0, 0, 0, b_in, nullptr, 0);
    // 4) u' = x1 * silu(z) * rinv
    k_act<<<B_ * L_ * D_ / 256, 256>>>();
    // 5) QTX = E^T @ u'  per batch  (M=KE, N=D, K=L)
    gemm64<true, EPI_NONE, false><<<dim3(KE / 64, D_ / 64, B_), 256>>>(
        EigVecs, p_u, p_G, L_, KE, D_, D_,
        (long)L_ * KE, (long)L_ * D_, (long)KE * D_, nullptr, nullptr, 0);
    // 6) G = QTX * W(b,k,d)
    k_w<<<B_ * (KE / 64), 128>>>(EigVals);
    // 7) v = silu(rinv * (E @ G))  per batch  (M=L, N=D, K=KE)
    gemm64<false, EPI_SILU, false><<<dim3(L_ / 64, D_ / 64, B_), 256>>>(
        EigVecs, p_G, p_v, KE, KE, D_, D_,
        (long)L_ * KE, (long)KE * D_, (long)L_ * D_, nullptr, p_rinv, L_);
    // 8) y = v @ W_out + b_out  (M=8192, N=128, K=128)
    gemm64<false, EPI_BIAS, false><<<dim3(B_ * L_ / 64, D_ / 64, 1), 256>>>(
        p_v, W_out, y, D_, D_, D_, D_, 0, 0, 0, b_out, nullptr, 0);
}

// round 6
// speedup vs baseline: 1.5121x; 1.5121x over previous
#include <cuda_runtime.h>
#include <cuda_bf16.h>
#include <math.h>
#include <stdint.h>

// Problem constants
static constexpr int B_ = 8;
static constexpr int L_ = 1024;
static constexpr int KE = 1024;   // eigvecs
static constexpr int D_ = 128;
static constexpr int S_ = 16;

// ---------------- scratch (device globals; no allocation allowed) ----------
__device__ float g_rinv[B_ * L_];
__device__ float g_h[(long)B_ * L_ * 2 * D_];        // in-proj out
__device__ float g_G[(long)B_ * KE * D_];            // QTX fp32 [b][k][d]
__device__ float g_v[(long)B_ * L_ * D_];            // silu(yssm)
__device__ __nv_bfloat16 g_Eh[(long)B_ * L_ * KE];   // E hi  [b][l][k]
__device__ __nv_bfloat16 g_El[(long)B_ * L_ * KE];   // E lo
__device__ __nv_bfloat16 g_uh[(long)B_ * L_ * D_];   // u' hi [b][l][d]
__device__ __nv_bfloat16 g_ul[(long)B_ * L_ * D_];
__device__ __nv_bfloat16 g_Gh[(long)B_ * KE * D_];   // G hi [b][k][d]
__device__ __nv_bfloat16 g_Gl[(long)B_ * KE * D_];
__device__ float g_ar[D_ * S_];
__device__ float g_ai[D_ * S_];
__device__ float g_bc[D_ * S_];
__device__ float g_bns[D_];
__device__ float g_bnb[D_];

// ---------------- helpers ----------------------------------------------------
__device__ __forceinline__ uint32_t smem_u32(const void* p) {
    uint32_t a;
    asm("{ .reg .u64 t; cvta.to.shared.u64 t, %1; cvt.u32.u64 %0, t; }" : "=r"(a) : "l"(p));
    return a;
}
__device__ __forceinline__ void split2(float x, __nv_bfloat16& h, __nv_bfloat16& l) {
    h = __float2bfloat16_rn(x);
    l = __float2bfloat16_rn(x - __bfloat162float(h));
}

#define CP16(dst, src) \
    asm volatile("cp.async.ca.shared.global [%0], [%1], 16;" :: "r"(dst), "l"(src))
#define CP_COMMIT() asm volatile("cp.async.commit_group;" ::: "memory")
#define CP_WAIT(n)  asm volatile("cp.async.wait_group %0;" :: "n"(n) : "memory")

__device__ __forceinline__ void ldm_x4(uint32_t* r, uint32_t a) {
    asm volatile("ldmatrix.sync.aligned.m8n8.x4.shared.b16 {%0,%1,%2,%3}, [%4];"
        : "=r"(r[0]), "=r"(r[1]), "=r"(r[2]), "=r"(r[3]) : "r"(a));
}
__device__ __forceinline__ void ldm_x4t(uint32_t* r, uint32_t a) {
    asm volatile("ldmatrix.sync.aligned.m8n8.x4.trans.shared.b16 {%0,%1,%2,%3}, [%4];"
        : "=r"(r[0]), "=r"(r[1]), "=r"(r[2]), "=r"(r[3]) : "r"(a));
}
__device__ __forceinline__ void mma_bf16(float* c, const uint32_t* a, uint32_t b0, uint32_t b1) {
    asm volatile("mma.sync.aligned.m16n8k16.row.col.f32.bf16.bf16.f32 "
        "{%0,%1,%2,%3}, {%4,%5,%6,%7}, {%8,%9}, {%0,%1,%2,%3};"
        : "+f"(c[0]), "+f"(c[1]), "+f"(c[2]), "+f"(c[3])
        : "r"(a[0]), "r"(a[1]), "r"(a[2]), "r"(a[3]), "r"(b0), "r"(b1));
}

// ---------------- prep: SSM tables + batchnorm fold -------------------------
__global__ void k_prep(const float* __restrict__ gamma, const float* __restrict__ beta,
                       const float* __restrict__ mean,  const float* __restrict__ var,
                       const float* __restrict__ log_Delta,
                       const float* __restrict__ Bp,    const float* __restrict__ Cp,
                       const float* __restrict__ log_A_real,
                       const float* __restrict__ A_imag)
{
    int idx = blockIdx.x * blockDim.x + threadIdx.x;
    if (idx < D_ * S_) {
        int d = idx / S_;
        float delta = expf(log_Delta[d]);
        float aRe = -expf(log_A_real[idx]);
        float aIm = A_imag[idx];
        float mag = expf(-1e-3f + delta * aRe);
        float sn, cs;
        sincosf(delta * aIm, &sn, &cs);
        g_ar[idx] = mag * cs;
        g_ai[idx] = mag * sn;
        g_bc[idx] = delta * Bp[idx] * Cp[idx];
    } else if (idx < D_ * S_ + D_) {
        int d = idx - D_ * S_;
        float sc = gamma[d] * rsqrtf(var[d] + 1e-5f);
        g_bns[d] = sc;
        g_bnb[d] = beta[d] - mean[d] * sc;
    }
}

// ---------------- row inverse-norms of EigVecs ------------------------------
__global__ void k_rinv(const float* __restrict__ E)
{
    int row = blockIdx.x * 8 + (threadIdx.x >> 5);
    int lane = threadIdx.x & 31;
    const float* p = E + (long)row * KE;
    float s = 0.f;
#pragma unroll
    for (int i = 0; i < KE / 32; i++) { float v = p[lane + 32 * i]; s += v * v; }
#pragma unroll
    for (int o = 16; o; o >>= 1) s += __shfl_xor_sync(0xffffffffu, s, o);
    if (lane == 0) g_rinv[row] = (s > 0.f) ? (1.0f / sqrtf(s)) : 0.f;
}

// ---------------- E -> bf16 hi/lo -------------------------------------------
__global__ void k_ecvt(const float* __restrict__ E)
{
    long i = (long)blockIdx.x * 256 + threadIdx.x;   // over n/4
    float4 v = ((const float4*)E)[i];
    __nv_bfloat162 h01, h23, l01, l23;
    h01.x = __float2bfloat16_rn(v.x); l01.x = __float2bfloat16_rn(v.x - __bfloat162float(h01.x));
    h01.y = __float2bfloat16_rn(v.y); l01.y = __float2bfloat16_rn(v.y - __bfloat162float(h01.y));
    h23.x = __float2bfloat16_rn(v.z); l23.x = __float2bfloat16_rn(v.z - __bfloat162float(h23.x));
    h23.y = __float2bfloat16_rn(v.w); l23.y = __float2bfloat16_rn(v.w - __bfloat162float(h23.y));
    ((__nv_bfloat162*)g_Eh)[2 * i]     = h01;
    ((__nv_bfloat162*)g_Eh)[2 * i + 1] = h23;
    ((__nv_bfloat162*)g_El)[2 * i]     = l01;
    ((__nv_bfloat162*)g_El)[2 * i + 1] = l23;
}

// ---------------- gated activation: u' = x1*silu(z)*rinv -> bf16 hi/lo -------
__global__ void k_act()
{
    long idx = (long)blockIdx.x * 256 + threadIdx.x;   // over B*L*D
    int m = (int)(idx >> 7);
    float x1 = g_h[(long)m * 256 + (idx & 127)];
    float z  = g_h[(long)m * 256 + 128 + (idx & 127)];
    float u  = x1 * (z / (1.f + expf(-z))) * g_rinv[m];
    __nv_bfloat16 h, l;
    split2(u, h, l);
    g_uh[idx] = h;
    g_ul[idx] = l;
}

// ---------------- SSM weight: G = QTX * W(b,k,d) -> bf16 hi/lo ---------------
__global__ void k_w(const float* __restrict__ EigVals)
{
    int blk = blockIdx.x;               // B * (KE/64)
    int b  = blk >> 4;
    int k0 = (blk & 15) << 6;
    int d  = threadIdx.x;               // 128
    float lar[S_], lai[S_], lbc[S_];
#pragma unroll
    for (int s = 0; s < S_; s++) {
        lar[s] = g_ar[d * S_ + s];
        lai[s] = g_ai[d * S_ + s];
        lbc[s] = g_bc[d * S_ + s];
    }
#pragma unroll 4
    for (int kk = 0; kk < 64; kk++) {
        int k = k0 + kk;
        float e = 1.0f - __ldg(&EigVals[b * KE + k]);
        float acc = 0.f;
#pragma unroll
        for (int s = 0; s < S_; s++) {
            float x = e * lar[s];
            float y = e * lai[s];
            float omx = 1.f - x;
            acc += __fdividef(x * omx - y * y, omx * omx + y * y) * lbc[s];
        }
        long gi = ((long)(b * KE + k)) * D_ + d;
        float val = g_G[gi] * acc;
        __nv_bfloat16 h, l;
        split2(val, h, l);
        g_Gh[gi] = h;
        g_Gl[gi] = l;
    }
}

// ---------------- split-bf16 HMMA GEMM ---------------------------------------
// C[b][m][n] (M=1024, N=128) = sum_c opA[m][c] * Bm[c][n], per batch b.
// TRANSA=false: A stored [m][c] (row-major, ld=1024)  -> ldmatrix.x4
// TRANSA=true : A stored [c][m] (E for QTX)           -> ldmatrix.x4.trans
// B stored [c][n], ld = 128.
// EPI: 0 = plain fp32 store, 1 = v = silu(rinv[m] * acc)
template <bool TRANSA, int EPI>
__global__ __launch_bounds__(256, 1)
void mma_gemm(const __nv_bfloat16* __restrict__ Ah, const __nv_bfloat16* __restrict__ Al,
              const __nv_bfloat16* __restrict__ Bh, const __nv_bfloat16* __restrict__ Bl,
              float* __restrict__ C, const float* __restrict__ rinv)
{
    constexpr int A_SZ  = TRANSA ? 32 * 72 * 2 : 64 * 40 * 2;   // bytes (one of hi/lo)
    constexpr int ASTRB = TRANSA ? 144 : 80;                    // row stride bytes
    constexpr int B_SZ  = 32 * 136 * 2;
    constexpr int BSTRB = 272;
    constexpr int STAGE = 2 * A_SZ + 2 * B_SZ;
    constexpr int NCH   = 1024 / 32;

    extern __shared__ char smem[];
    const uint32_t sb = smem_u32(smem);

    const int tid  = threadIdx.x;
    const int lane = tid & 31;
    const int wid  = tid >> 5;
    const int wm   = wid & 1;          // 2 warps along M
    const int wn   = wid >> 1;         // 4 warps along N
    const int m_w  = wm * 32;
    const int n_w  = wn * 32;
    const int b    = blockIdx.y;
    const int m0   = blockIdx.x * 64;

    // global load indices (per thread, fixed across chunks)
    const int ar = TRANSA ? (tid >> 3) : (tid >> 2);       // A row within tile
    const int ac = TRANSA ? (tid & 7)  : (tid & 3);        // A 16B-col
    const int br = tid >> 3;                               // B rows: idx>>4 with idx=tid*2+q
    // (B handled with explicit idx below)

    float acc[2][4][4];
#pragma unroll
    for (int i = 0; i < 2; i++)
#pragma unroll
        for (int j = 0; j < 4; j++)
#pragma unroll
            for (int q = 0; q < 4; q++) acc[i][j][q] = 0.f;

    auto issue_chunk = [&](int ch) {
        const uint32_t st = sb + (uint32_t)(ch & 1) * STAGE;
        // A tile
        if (TRANSA) {
            // rows = contraction (32), cols = m (64)
            long g = ((long)(b * 1024 + ch * 32 + ar)) * 1024 + m0 + ac * 8;
            uint32_t dst = st + ar * ASTRB + ac * 16;
            CP16(dst,        Ah + g);
            CP16(dst + A_SZ, Al + g);
        } else {
            // rows = m (64), cols = contraction (32)
            long g = ((long)(b * 1024 + m0 + ar)) * 1024 + ch * 32 + ac * 8;
            uint32_t dst = st + ar * ASTRB + ac * 16;
            CP16(dst,        Ah + g);
            CP16(dst + A_SZ, Al + g);
        }
        // B tile: 32 rows x 128 cols = 512 x 16B; 2 per thread
#pragma unroll
        for (int q = 0; q < 2; q++) {
            int idx = tid + q * 256;
            int row = idx >> 4, c4 = idx & 15;
            long g = ((long)(b * 1024 + ch * 32 + row)) * 128 + c4 * 8;
            uint32_t dst = st + 2 * A_SZ + row * BSTRB + c4 * 16;
            CP16(dst,        Bh + g);
            CP16(dst + B_SZ, Bl + g);
        }
        CP_COMMIT();
    };

    issue_chunk(0);

    for (int ch = 0; ch < NCH; ++ch) {
        if (ch + 1 < NCH) { issue_chunk(ch + 1); CP_WAIT(1); }
        else              { CP_WAIT(0); }
        __syncthreads();

        const uint32_t st = sb + (uint32_t)(ch & 1) * STAGE;
        const uint32_t aOff = st;
        const uint32_t bOff = st + 2 * A_SZ;

        // ---- load fragments ----
        uint32_t ah[2][2][4], al[2][2][4];
#pragma unroll
        for (int mi = 0; mi < 2; mi++)
#pragma unroll
            for (int kk = 0; kk < 2; kk++) {
                uint32_t addr;
                if (TRANSA) {
                    int g = lane >> 3, r = lane & 7;
                    int row = kk * 16 + ((g & 2) ? 8 : 0) + r;
                    int col = m_w + mi * 16 + ((g & 1) ? 8 : 0);
                    addr = aOff + row * ASTRB + col * 2;
                    ldm_x4t(ah[mi][kk], addr);
                    ldm_x4t(al[mi][kk], addr + A_SZ);
                } else {
                    int row = m_w + mi * 16 + (lane & 15);
                    int col = kk * 16 + (lane >> 4) * 8;
                    addr = aOff + row * ASTRB + col * 2;
                    ldm_x4(ah[mi][kk], addr);
                    ldm_x4(al[mi][kk], addr + A_SZ);
                }
            }
        uint32_t bh[2][2][4], bl[2][2][4];    // [n16 idx][kk]
#pragma unroll
        for (int bi = 0; bi < 2; bi++)
#pragma unroll
            for (int kk = 0; kk < 2; kk++) {
                int g = lane >> 3, r = lane & 7;
                int row = kk * 16 + ((g & 2) ? 8 : 0) + r;
                int col = n_w + bi * 16 + ((g & 1) ? 8 : 0);
                uint32_t addr = bOff + row * BSTRB + col * 2;
                ldm_x4t(bh[bi][kk], addr);
                ldm_x4t(bl[bi][kk], addr + B_SZ);
            }

        // ---- mma: hh + lh + hl ----
#pragma unroll
        for (int mi = 0; mi < 2; mi++)
#pragma unroll
            for (int bi = 0; bi < 2; bi++)
#pragma unroll
                for (int sub = 0; sub < 2; sub++) {
                    float* c = acc[mi][bi * 2 + sub];
#pragma unroll
                    for (int kk = 0; kk < 2; kk++) {
                        uint32_t bh0 = bh[bi][kk][sub], bh1 = bh[bi][kk][sub + 2];
                        uint32_t bl0 = bl[bi][kk][sub], bl1 = bl[bi][kk][sub + 2];
                        mma_bf16(c, ah[mi][kk], bh0, bh1);
                        mma_bf16(c, al[mi][kk], bh0, bh1);
                        mma_bf16(c, ah[mi][kk], bl0, bl1);
                    }
                }
        __syncthreads();
    }

    // ---- epilogue ----
#pragma unroll
    for (int mi = 0; mi < 2; mi++) {
        int r0 = m0 + m_w + mi * 16 + (lane >> 2);
        int r1 = r0 + 8;
        float rs0 = 1.f, rs1 = 1.f;
        if (EPI == 1) {
            rs0 = rinv[b * 1024 + r0];
            rs1 = rinv[b * 1024 + r1];
        }
#pragma unroll
        for (int ni = 0; ni < 4; ni++) {
            int col = n_w + ni * 8 + (lane & 3) * 2;
            float v0 = acc[mi][ni][0], v1 = acc[mi][ni][1];
            float v2 = acc[mi][ni][2], v3 = acc[mi][ni][3];
            if (EPI == 1) {
                v0 *= rs0; v1 *= rs0; v2 *= rs1; v3 *= rs1;
                v0 = v0 / (1.f + expf(-v0));
                v1 = v1 / (1.f + expf(-v1));
                v2 = v2 / (1.f + expf(-v2));
                v3 = v3 / (1.f + expf(-v3));
            }
            float2* p0 = (float2*)(C + ((long)(b * 1024 + r0)) * 128 + col);
            float2* p1 = (float2*)(C + ((long)(b * 1024 + r1)) * 128 + col);
            *p0 = make_float2(v0, v1);
            *p1 = make_float2(v2, v3);
        }
    }
}

// ---------------- generic 64x64x16 SGEMM (fp32 in/out proj) -----------------
enum { EPI_NONE = 0, EPI_BIAS = 1 };

template <int EPI, bool BNA>
__global__ __launch_bounds__(256)
void gemm64(const float* __restrict__ A, const float* __restrict__ Bm,
            float* __restrict__ C,
            int Kc, int lda, int ldb, int ldc,
            const float* __restrict__ bias)
{
    const int m0 = blockIdx.x * 64;
    const int n0 = blockIdx.y * 64;

    __shared__ float As[16][68];
    __shared__ float Bs[16][64];

    const int tid = threadIdx.x;
    const int tr = (tid >> 4) << 2;
    const int tc = (tid & 15) << 2;

    float acc[4][4] = {};

    for (int p0 = 0; p0 < Kc; p0 += 16) {
        {
            int r = tid >> 2;
            int c = (tid & 3) << 2;
            float4 av = *(const float4*)(A + (long)(m0 + r) * lda + p0 + c);
            if (BNA) {
                av.x = av.x * g_bns[p0 + c + 0] + g_bnb[p0 + c + 0];
                av.y = av.y * g_bns[p0 + c + 1] + g_bnb[p0 + c + 1];
                av.z = av.z * g_bns[p0 + c + 2] + g_bnb[p0 + c + 2];
                av.w = av.w * g_bns[p0 + c + 3] + g_bnb[p0 + c + 3];
            }
            As[c + 0][r] = av.x;
            As[c + 1][r] = av.y;
            As[c + 2][r] = av.z;
            As[c + 3][r] = av.w;
        }
        {
            int r = tid >> 4;
            int c = (tid & 15) << 2;
            *(float4*)&Bs[r][c] = *(const float4*)(Bm + (long)(p0 + r) * ldb + n0 + c);
        }
        __syncthreads();
#pragma unroll
        for (int kk = 0; kk < 16; kk++) {
            float af[4], bf[4];
            *(float4*)af = *(const float4*)&As[kk][tr];
            *(float4*)bf = *(const float4*)&Bs[kk][tc];
#pragma unroll
            for (int i = 0; i < 4; i++)
#pragma unroll
                for (int j = 0; j < 4; j++)
                    acc[i][j] += af[i] * bf[j];
        }
        __syncthreads();
    }

#pragma unroll
    for (int i = 0; i < 4; i++) {
        int row = m0 + tr + i;
        float4 o;
        o.x = acc[i][0]; o.y = acc[i][1]; o.z = acc[i][2]; o.w = acc[i][3];
        if (EPI == EPI_BIAS) {
            o.x += bias[n0 + tc + 0];
            o.y += bias[n0 + tc + 1];
            o.z += bias[n0 + tc + 2];
            o.w += bias[n0 + tc + 3];
        }
        *(float4*)(C + (long)row * ldc + n0 + tc) = o;
    }
}

// ---------------- launch ----------------------------------------------------
extern "C" void kernel_launch(void* const* d_in, const int* in_sizes, int n_in,
                              void* d_out, int out_size)
{
    const float* x        = (const float*)d_in[0];
    const float* EigVecs  = (const float*)d_in[2];
    const float* EigVals  = (const float*)d_in[3];
    const float* bn_gamma = (const float*)d_in[4];
    const float* bn_beta  = (const float*)d_in[5];
    const float* bn_mean  = (const float*)d_in[6];
    const float* bn_var   = (const float*)d_in[7];
    const float* W_in     = (const float*)d_in[8];
    const float* b_in     = (const float*)d_in[9];
    const float* log_Delta= (const float*)d_in[10];
    const float* Bp       = (const float*)d_in[11];
    const float* Cp       = (const float*)d_in[12];
    const float* log_A    = (const float*)d_in[13];
    const float* A_imag   = (const float*)d_in[14];
    const float* W_out    = (const float*)d_in[15];
    const float* b_out    = (const float*)d_in[16];
    float* y = (float*)d_out;

    float *p_h, *p_v, *p_G, *p_rinv;
    __nv_bfloat16 *p_Eh, *p_El, *p_uh, *p_ul, *p_Gh, *p_Gl;
    cudaGetSymbolAddress((void**)&p_h, g_h);
    cudaGetSymbolAddress((void**)&p_v, g_v);
    cudaGetSymbolAddress((void**)&p_G, g_G);
    cudaGetSymbolAddress((void**)&p_rinv, g_rinv);
    cudaGetSymbolAddress((void**)&p_Eh, g_Eh);
    cudaGetSymbolAddress((void**)&p_El, g_El);
    cudaGetSymbolAddress((void**)&p_uh, g_uh);
    cudaGetSymbolAddress((void**)&p_ul, g_ul);
    cudaGetSymbolAddress((void**)&p_Gh, g_Gh);
    cudaGetSymbolAddress((void**)&p_Gl, g_Gl);

    // dynamic smem sizes (2 stages)
    const int SMEM_T = 2 * (2 * (32 * 72 * 2) + 2 * (32 * 136 * 2));  // 53248
    const int SMEM_F = 2 * (2 * (64 * 40 * 2) + 2 * (32 * 136 * 2));  // 55296
    cudaFuncSetAttribute(mma_gemm<true, 0>,  cudaFuncAttributeMaxDynamicSharedMemorySize, SMEM_T);
    cudaFuncSetAttribute(mma_gemm<false, 1>, cudaFuncAttributeMaxDynamicSharedMemorySize, SMEM_F);

    // 1) tables
    k_prep<<<(D_ * S_ + D_ + 255) / 256, 256>>>(bn_gamma, bn_beta, bn_mean, bn_var,
                                                log_Delta, Bp, Cp, log_A, A_imag);
    // 2) row norms
    k_rinv<<<B_ * L_ / 8, 256>>>(EigVecs);
    // 3) E -> bf16 hi/lo
    k_ecvt<<<(int)((long)B_ * L_ * KE / 4 / 256), 256>>>(EigVecs);
    // 4) in-proj: h = bn(x) @ W_in + b_in   (M=8192, N=256, K=128)
    gemm64<EPI_BIAS, true><<<dim3(B_ * L_ / 64, 256 / 64), 256>>>(
        x, W_in, p_h, D_, D_, 2 * D_, 2 * D_, b_in);
    // 5) u' = x1 * silu(z) * rinv -> bf16 hi/lo
    k_act<<<B_ * L_ * D_ / 256, 256>>>();
    // 6) QTX[b][k][d] = sum_l E[l][k] * u'[l][d]   (A = E^T via ldmatrix.trans)
    mma_gemm<true, 0><<<dim3(KE / 64, B_), 256, SMEM_T>>>(
        p_Eh, p_El, p_uh, p_ul, p_G, nullptr);
    // 7) G = QTX * W(b,k,d) -> bf16 hi/lo
    k_w<<<B_ * (KE / 64), D_>>>(EigVals);
    // 8) v[b][l][d] = silu(rinv * sum_k E[l][k] * G[k][d])
    mma_gemm<false, 1><<<dim3(L_ / 64, B_), 256, SMEM_F>>>(
        p_Eh, p_El, p_Gh, p_Gl, p_v, p_rinv);
    // 9) y = v @ W_out + b_out  (M=8192, N=128, K=128)
    gemm64<EPI_BIAS, false><<<dim3(B_ * L_ / 64, D_ / 64), 256>>>(
        p_v, W_out, y, D_, D_, D_, D_, b_out);
}

// round 8
// speedup vs baseline: 1.7518x; 1.1585x over previous
#include <cuda_runtime.h>
#include <cuda_bf16.h>
#include <math.h>
#include <stdint.h>

// Problem constants
static constexpr int B_ = 8;
static constexpr int L_ = 1024;
static constexpr int KE = 1024;
static constexpr int D_ = 128;
static constexpr int S_ = 16;

// ---------------- scratch (device globals) ----------------------------------
__device__ float g_rinv[B_ * L_];
__device__ float g_G[(long)B_ * KE * D_];            // QTX fp32 [b][k][d]
__device__ __nv_bfloat16 g_Eh[(long)B_ * L_ * KE];
__device__ __nv_bfloat16 g_El[(long)B_ * L_ * KE];
__device__ __nv_bfloat16 g_xh[(long)B_ * L_ * D_];   // bn(x) hi/lo
__device__ __nv_bfloat16 g_xl[(long)B_ * L_ * D_];
__device__ __nv_bfloat16 g_uh[(long)B_ * L_ * D_];   // u' = x1*silu(z)*rinv
__device__ __nv_bfloat16 g_ul[(long)B_ * L_ * D_];
__device__ __nv_bfloat16 g_Gh[(long)B_ * KE * D_];
__device__ __nv_bfloat16 g_Gl[(long)B_ * KE * D_];
__device__ __nv_bfloat16 g_vh[(long)B_ * L_ * D_];   // silu(yssm)
__device__ __nv_bfloat16 g_vl[(long)B_ * L_ * D_];
__device__ __nv_bfloat16 g_Wih[D_ * 2 * D_];         // W_in packed (x1,z interleaved)
__device__ __nv_bfloat16 g_Wil[D_ * 2 * D_];
__device__ __nv_bfloat16 g_Woh[D_ * D_];
__device__ __nv_bfloat16 g_Wol[D_ * D_];
__device__ float g_bp[2 * D_];                       // b_in packed
__device__ float g_ar[D_ * S_];
__device__ float g_ai[D_ * S_];
__device__ float g_bc[D_ * S_];
__device__ float g_bns[D_];
__device__ float g_bnb[D_];

// ---------------- helpers ----------------------------------------------------
__device__ __forceinline__ uint32_t smem_u32(const void* p) {
    uint32_t a;
    asm("{ .reg .u64 t; cvta.to.shared.u64 t, %1; cvt.u32.u64 %0, t; }" : "=r"(a) : "l"(p));
    return a;
}
__device__ __forceinline__ void split2(float x, __nv_bfloat16& h, __nv_bfloat16& l) {
    h = __float2bfloat16_rn(x);
    l = __float2bfloat16_rn(x - __bfloat162float(h));
}

#define CP16(dst, src) \
    asm volatile("cp.async.ca.shared.global [%0], [%1], 16;" :: "r"(dst), "l"(src))
#define CP_COMMIT() asm volatile("cp.async.commit_group;" ::: "memory")
#define CP_WAIT(n)  asm volatile("cp.async.wait_group %0;" :: "n"(n) : "memory")

__device__ __forceinline__ void ldm_x4(uint32_t* r, uint32_t a) {
    asm volatile("ldmatrix.sync.aligned.m8n8.x4.shared.b16 {%0,%1,%2,%3}, [%4];"
        : "=r"(r[0]), "=r"(r[1]), "=r"(r[2]), "=r"(r[3]) : "r"(a));
}
__device__ __forceinline__ void ldm_x4t(uint32_t* r, uint32_t a) {
    asm volatile("ldmatrix.sync.aligned.m8n8.x4.trans.shared.b16 {%0,%1,%2,%3}, [%4];"
        : "=r"(r[0]), "=r"(r[1]), "=r"(r[2]), "=r"(r[3]) : "r"(a));
}
__device__ __forceinline__ void mma_bf16(float* c, const uint32_t* a, uint32_t b0, uint32_t b1) {
    asm volatile("mma.sync.aligned.m16n8k16.row.col.f32.bf16.bf16.f32 "
        "{%0,%1,%2,%3}, {%4,%5,%6,%7}, {%8,%9}, {%0,%1,%2,%3};"
        : "+f"(c[0]), "+f"(c[1]), "+f"(c[2]), "+f"(c[3])
        : "r"(a[0]), "r"(a[1]), "r"(a[2]), "r"(a[3]), "r"(b0), "r"(b1));
}
__device__ __forceinline__ float silu(float v) { return v / (1.f + expf(-v)); }

// ---------------- prep: SSM tables + BN fold + weight pack/split ------------
__global__ void k_prep(const float* __restrict__ gamma, const float* __restrict__ beta,
                       const float* __restrict__ mean,  const float* __restrict__ var,
                       const float* __restrict__ log_Delta,
                       const float* __restrict__ Bp,    const float* __restrict__ Cp,
                       const float* __restrict__ log_A_real,
                       const float* __restrict__ A_imag,
                       const float* __restrict__ W_in,  const float* __restrict__ b_in,
                       const float* __restrict__ W_out)
{
    int idx = blockIdx.x * blockDim.x + threadIdx.x;
    if (idx < 2048) {                    // D*S
        int d = idx / S_;
        float delta = expf(log_Delta[d]);
        float aRe = -expf(log_A_real[idx]);
        float aIm = A_imag[idx];
        float mag = expf(-1e-3f + delta * aRe);
        float sn, cs;
        sincosf(delta * aIm, &sn, &cs);
        g_ar[idx] = mag * cs;
        g_ai[idx] = mag * sn;
        g_bc[idx] = delta * Bp[idx] * Cp[idx];
    } else if (idx < 2048 + 128) {       // BN fold
        int d = idx - 2048;
        float sc = gamma[d] * rsqrtf(var[d] + 1e-5f);
        g_bns[d] = sc;
        g_bnb[d] = beta[d] - mean[d] * sc;
    } else if (idx < 2048 + 128 + 32768) {   // W_in pack + split
        int j = idx - (2048 + 128);
        int c = j >> 8, n = j & 255;
        int d = n >> 1, half = n & 1;
        float w = W_in[c * 256 + half * 128 + d];
        __nv_bfloat16 h, l;
        split2(w, h, l);
        g_Wih[j] = h; g_Wil[j] = l;
    } else if (idx < 2048 + 128 + 32768 + 16384) {  // W_out split
        int j = idx - (2048 + 128 + 32768);
        float w = W_out[j];
        __nv_bfloat16 h, l;
        split2(w, h, l);
        g_Woh[j] = h; g_Wol[j] = l;
    } else if (idx < 2048 + 128 + 32768 + 16384 + 256) {  // bias pack
        int j = idx - (2048 + 128 + 32768 + 16384);
        g_bp[j] = b_in[(j & 1) * 128 + (j >> 1)];
    }
}

// ---------------- fused: row inv-norm + E -> bf16 hi/lo ---------------------
__global__ void k_erow(const float* __restrict__ E)
{
    int row = blockIdx.x * 8 + (threadIdx.x >> 5);
    int lane = threadIdx.x & 31;
    const float4* p = (const float4*)(E + (long)row * KE);
    __nv_bfloat162* oh = (__nv_bfloat162*)(g_Eh + (long)row * KE);
    __nv_bfloat162* ol = (__nv_bfloat162*)(g_El + (long)row * KE);
    float s = 0.f;
#pragma unroll
    for (int i = 0; i < 8; i++) {
        int c4 = lane + i * 32;                 // float4 index
        float4 v = p[c4];
        s += v.x * v.x + v.y * v.y + v.z * v.z + v.w * v.w;
        __nv_bfloat162 h01, h23, l01, l23;
        h01.x = __float2bfloat16_rn(v.x); l01.x = __float2bfloat16_rn(v.x - __bfloat162float(h01.x));
        h01.y = __float2bfloat16_rn(v.y); l01.y = __float2bfloat16_rn(v.y - __bfloat162float(h01.y));
        h23.x = __float2bfloat16_rn(v.z); l23.x = __float2bfloat16_rn(v.z - __bfloat162float(h23.x));
        h23.y = __float2bfloat16_rn(v.w); l23.y = __float2bfloat16_rn(v.w - __bfloat162float(h23.y));
        oh[2 * c4] = h01; oh[2 * c4 + 1] = h23;
        ol[2 * c4] = l01; ol[2 * c4 + 1] = l23;
    }
#pragma unroll
    for (int o = 16; o; o >>= 1) s += __shfl_xor_sync(0xffffffffu, s, o);
    if (lane == 0) g_rinv[row] = (s > 0.f) ? (1.0f / sqrtf(s)) : 0.f;
}

// ---------------- x -> bn(x) bf16 hi/lo --------------------------------------
__global__ void k_xcvt(const float* __restrict__ x)
{
    long i = (long)blockIdx.x * 256 + threadIdx.x;   // float4 index
    int c = ((int)i & 31) * 4;                       // channel (128 per row, /4)
    float4 v = ((const float4*)x)[i];
    v.x = v.x * g_bns[c + 0] + g_bnb[c + 0];
    v.y = v.y * g_bns[c + 1] + g_bnb[c + 1];
    v.z = v.z * g_bns[c + 2] + g_bnb[c + 2];
    v.w = v.w * g_bns[c + 3] + g_bnb[c + 3];
    __nv_bfloat162 h01, h23, l01, l23;
    h01.x = __float2bfloat16_rn(v.x); l01.x = __float2bfloat16_rn(v.x - __bfloat162float(h01.x));
    h01.y = __float2bfloat16_rn(v.y); l01.y = __float2bfloat16_rn(v.y - __bfloat162float(h01.y));
    h23.x = __float2bfloat16_rn(v.z); l23.x = __float2bfloat16_rn(v.z - __bfloat162float(h23.x));
    h23.y = __float2bfloat16_rn(v.w); l23.y = __float2bfloat16_rn(v.w - __bfloat162float(h23.y));
    ((__nv_bfloat162*)g_xh)[2 * i] = h01; ((__nv_bfloat162*)g_xh)[2 * i + 1] = h23;
    ((__nv_bfloat162*)g_xl)[2 * i] = l01; ((__nv_bfloat162*)g_xl)[2 * i + 1] = l23;
}

// ---------------- SSM weight: G = QTX * W(b,k,d) -> bf16 hi/lo ---------------
__global__ void k_w(const float* __restrict__ EigVals)
{
    int blk = blockIdx.x;
    int b  = blk >> 4;
    int k0 = (blk & 15) << 6;
    int d  = threadIdx.x;
    float lar[S_], lai[S_], lbc[S_];
#pragma unroll
    for (int s = 0; s < S_; s++) {
        lar[s] = g_ar[d * S_ + s];
        lai[s] = g_ai[d * S_ + s];
        lbc[s] = g_bc[d * S_ + s];
    }
#pragma unroll 4
    for (int kk = 0; kk < 64; kk++) {
        int k = k0 + kk;
        float e = 1.0f - __ldg(&EigVals[b * KE + k]);
        float acc = 0.f;
#pragma unroll
        for (int s = 0; s < S_; s++) {
            float x = e * lar[s];
            float y = e * lai[s];
            float omx = 1.f - x;
            acc += __fdividef(x * omx - y * y, omx * omx + y * y) * lbc[s];
        }
        long gi = ((long)(b * KE + k)) * D_ + d;
        float val = g_G[gi] * acc;
        __nv_bfloat16 h, l;
        split2(val, h, l);
        g_Gh[gi] = h;
        g_Gl[gi] = l;
    }
}

// ---------------- split-bf16 HMMA GEMM ---------------------------------------
// Per batch b (blockIdx.y): C[m][n] = sum_c opA[m][c] * B[c][n]; M=1024/batch,
// CTA tile 64(M) x 128(N); n0 = blockIdx.z*128 (B col offset).
// EPI 0: fp32 store to Cf
// EPI 1: silu(rinv*acc) -> bf16 hi/lo (Ch/Cl)
// EPI 2: gated pairs (x1,z)=cols(2d,2d+1): u=(x1+bias)*silu(z+bias)*rinv -> bf16 hi/lo at col d
// EPI 3: acc + bias -> fp32 store to Cf
template <bool TRANSA, int EPI>
__global__ __launch_bounds__(256, 1)
void mma_gemm(const __nv_bfloat16* __restrict__ Ah, const __nv_bfloat16* __restrict__ Al,
              const __nv_bfloat16* __restrict__ Bh, const __nv_bfloat16* __restrict__ Bl,
              float* __restrict__ Cf, __nv_bfloat16* __restrict__ Ch, __nv_bfloat16* __restrict__ Cl,
              const float* __restrict__ rinv, const float* __restrict__ bias,
              int nch, int lda, int ldb, long aStr, long bStr, long cStr)
{
    constexpr int A_SZ  = TRANSA ? 32 * 72 * 2 : 64 * 40 * 2;
    constexpr int ASTRB = TRANSA ? 144 : 80;
    constexpr int B_SZ  = 32 * 136 * 2;
    constexpr int BSTRB = 272;
    constexpr int STAGE = 2 * A_SZ + 2 * B_SZ;

    extern __shared__ char smem[];
    const uint32_t sb = smem_u32(smem);

    const int tid  = threadIdx.x;
    const int lane = tid & 31;
    const int wid  = tid >> 5;
    const int m_w  = (wid & 1) * 32;
    const int n_w  = (wid >> 1) * 32;
    const int b    = blockIdx.y;
    const int m0   = blockIdx.x * 64;
    const int n0   = blockIdx.z * 128;

    const int ar = TRANSA ? (tid >> 3) : (tid >> 2);
    const int ac = TRANSA ? (tid & 7)  : (tid & 3);

    float acc[2][4][4];
#pragma unroll
    for (int i = 0; i < 2; i++)
#pragma unroll
        for (int j = 0; j < 4; j++)
#pragma unroll
            for (int q = 0; q < 4; q++) acc[i][j][q] = 0.f;

    auto issue_chunk = [&](int ch) {
        const uint32_t st = sb + (uint32_t)(ch & 1) * STAGE;
        long g;
        if (TRANSA) g = (long)b * aStr + (long)(ch * 32 + ar) * lda + m0 + ac * 8;
        else        g = (long)b * aStr + (long)(m0 + ar) * lda + ch * 32 + ac * 8;
        uint32_t dst = st + ar * ASTRB + ac * 16;
        CP16(dst,        Ah + g);
        CP16(dst + A_SZ, Al + g);
#pragma unroll
        for (int q = 0; q < 2; q++) {
            int idx = tid + q * 256;
            int row = idx >> 4, c4 = idx & 15;
            long gb = (long)b * bStr + (long)(ch * 32 + row) * ldb + n0 + c4 * 8;
            uint32_t d2 = st + 2 * A_SZ + row * BSTRB + c4 * 16;
            CP16(d2,        Bh + gb);
            CP16(d2 + B_SZ, Bl + gb);
        }
        CP_COMMIT();
    };

    issue_chunk(0);

    for (int ch = 0; ch < nch; ++ch) {
        if (ch + 1 < nch) { issue_chunk(ch + 1); CP_WAIT(1); }
        else              { CP_WAIT(0); }
        __syncthreads();

        const uint32_t st = sb + (uint32_t)(ch & 1) * STAGE;
        const uint32_t aOff = st;
        const uint32_t bOff = st + 2 * A_SZ;

        uint32_t ah[2][2][4], al[2][2][4];
#pragma unroll
        for (int mi = 0; mi < 2; mi++)
#pragma unroll
            for (int kk = 0; kk < 2; kk++) {
                uint32_t addr;
                if (TRANSA) {
                    int g = lane >> 3, r = lane & 7;
                    int row = kk * 16 + ((g & 2) ? 8 : 0) + r;
                    int col = m_w + mi * 16 + ((g & 1) ? 8 : 0);
                    addr = aOff + row * ASTRB + col * 2;
                    ldm_x4t(ah[mi][kk], addr);
                    ldm_x4t(al[mi][kk], addr + A_SZ);
                } else {
                    int row = m_w + mi * 16 + (lane & 15);
                    int col = kk * 16 + (lane >> 4) * 8;
                    addr = aOff + row * ASTRB + col * 2;
                    ldm_x4(ah[mi][kk], addr);
                    ldm_x4(al[mi][kk], addr + A_SZ);
                }
            }
        uint32_t bh[2][2][4], bl[2][2][4];
#pragma unroll
        for (int bi = 0; bi < 2; bi++)
#pragma unroll
            for (int kk = 0; kk < 2; kk++) {
                int g = lane >> 3, r = lane & 7;
                int row = kk * 16 + ((g & 2) ? 8 : 0) + r;
                int col = n_w + bi * 16 + ((g & 1) ? 8 : 0);
                uint32_t addr = bOff + row * BSTRB + col * 2;
                ldm_x4t(bh[bi][kk], addr);
                ldm_x4t(bl[bi][kk], addr + B_SZ);
            }

#pragma unroll
        for (int mi = 0; mi < 2; mi++)
#pragma unroll
            for (int bi = 0; bi < 2; bi++)
#pragma unroll
                for (int sub = 0; sub < 2; sub++) {
                    float* c = acc[mi][bi * 2 + sub];
#pragma unroll
                    for (int kk = 0; kk < 2; kk++) {
                        uint32_t bh0 = bh[bi][kk][sub], bh1 = bh[bi][kk][sub + 2];
                        uint32_t bl0 = bl[bi][kk][sub], bl1 = bl[bi][kk][sub + 2];
                        mma_bf16(c, ah[mi][kk], bh0, bh1);
                        mma_bf16(c, al[mi][kk], bh0, bh1);
                        mma_bf16(c, ah[mi][kk], bl0, bl1);
                    }
                }
        __syncthreads();
    }

    // ---- epilogue ----
#pragma unroll
    for (int mi = 0; mi < 2; mi++) {
        int r0 = m0 + m_w + mi * 16 + (lane >> 2);
        int r1 = r0 + 8;
        float rs0 = 1.f, rs1 = 1.f;
        if (EPI == 1 || EPI == 2) {
            rs0 = rinv[b * 1024 + r0];
            rs1 = rinv[b * 1024 + r1];
        }
#pragma unroll
        for (int ni = 0; ni < 4; ni++) {
            int col = n_w + ni * 8 + (lane & 3) * 2;
            float v0 = acc[mi][ni][0], v1 = acc[mi][ni][1];
            float v2 = acc[mi][ni][2], v3 = acc[mi][ni][3];
            if (EPI == 0) {
                *(float2*)(Cf + (long)b * cStr + (long)r0 * 128 + col) = make_float2(v0, v1);
                *(float2*)(Cf + (long)b * cStr + (long)r1 * 128 + col) = make_float2(v2, v3);
            } else if (EPI == 3) {
                float b0 = bias[col], b1 = bias[col + 1];
                *(float2*)(Cf + (long)b * cStr + (long)r0 * 128 + col) = make_float2(v0 + b0, v1 + b1);
                *(float2*)(Cf + (long)b * cStr + (long)r1 * 128 + col) = make_float2(v2 + b0, v3 + b1);
            } else if (EPI == 1) {
                v0 = silu(v0 * rs0); v1 = silu(v1 * rs0);
                v2 = silu(v2 * rs1); v3 = silu(v3 * rs1);
                __nv_bfloat16 h, l;
                __nv_bfloat162 h01, l01, h23, l23;
                split2(v0, h, l); h01.x = h; l01.x = l;
                split2(v1, h, l); h01.y = h; l01.y = l;
                split2(v2, h, l); h23.x = h; l23.x = l;
                split2(v3, h, l); h23.y = h; l23.y = l;
                long o0 = (long)b * cStr + (long)r0 * 128 + col;
                long o1 = (long)b * cStr + (long)r1 * 128 + col;
                *(__nv_bfloat162*)(Ch + o0) = h01;
                *(__nv_bfloat162*)(Cl + o0) = l01;
                *(__nv_bfloat162*)(Ch + o1) = h23;
                *(__nv_bfloat162*)(Cl + o1) = l23;
            } else {  // EPI == 2 gated
                float bx = bias[n0 + col], bz = bias[n0 + col + 1];
                float u0 = (v0 + bx) * silu(v1 + bz) * rs0;
                float u1 = (v2 + bx) * silu(v3 + bz) * rs1;
                int dcol = blockIdx.z * 64 + (col >> 1);
                __nv_bfloat16 h0, l0, h1, l1;
                split2(u0, h0, l0);
                split2(u1, h1, l1);
                long o0 = (long)b * cStr + (long)r0 * 128 + dcol;
                long o1 = (long)b * cStr + (long)r1 * 128 + dcol;
                Ch[o0] = h0; Cl[o0] = l0;
                Ch[o1] = h1; Cl[o1] = l1;
            }
        }
    }
}

// ---------------- launch ----------------------------------------------------
extern "C" void kernel_launch(void* const* d_in, const int* in_sizes, int n_in,
                              void* d_out, int out_size)
{
    const float* x        = (const float*)d_in[0];
    const float* EigVecs  = (const float*)d_in[2];
    const float* EigVals  = (const float*)d_in[3];
    const float* bn_gamma = (const float*)d_in[4];
    const float* bn_beta  = (const float*)d_in[5];
    const float* bn_mean  = (const float*)d_in[6];
    const float* bn_var   = (const float*)d_in[7];
    const float* W_in     = (const float*)d_in[8];
    const float* b_in     = (const float*)d_in[9];
    const float* log_Delta= (const float*)d_in[10];
    const float* Bp       = (const float*)d_in[11];
    const float* Cp       = (const float*)d_in[12];
    const float* log_A    = (const float*)d_in[13];
    const float* A_imag   = (const float*)d_in[14];
    const float* W_out    = (const float*)d_in[15];
    const float* b_out    = (const float*)d_in[16];
    float* y = (float*)d_out;

    float *p_G, *p_rinv, *p_bp;
    __nv_bfloat16 *p_Eh, *p_El, *p_xh, *p_xl, *p_uh, *p_ul, *p_Gh, *p_Gl, *p_vh, *p_vl;
    __nv_bfloat16 *p_Wih, *p_Wil, *p_Woh, *p_Wol;
    cudaGetSymbolAddress((void**)&p_G, g_G);
    cudaGetSymbolAddress((void**)&p_rinv, g_rinv);
    cudaGetSymbolAddress((void**)&p_bp, g_bp);
    cudaGetSymbolAddress((void**)&p_Eh, g_Eh);
    cudaGetSymbolAddress((void**)&p_El, g_El);
    cudaGetSymbolAddress((void**)&p_xh, g_xh);
    cudaGetSymbolAddress((void**)&p_xl, g_xl);
    cudaGetSymbolAddress((void**)&p_uh, g_uh);
    cudaGetSymbolAddress((void**)&p_ul, g_ul);
    cudaGetSymbolAddress((void**)&p_Gh, g_Gh);
    cudaGetSymbolAddress((void**)&p_Gl, g_Gl);
    cudaGetSymbolAddress((void**)&p_vh, g_vh);
    cudaGetSymbolAddress((void**)&p_vl, g_vl);
    cudaGetSymbolAddress((void**)&p_Wih, g_Wih);
    cudaGetSymbolAddress((void**)&p_Wil, g_Wil);
    cudaGetSymbolAddress((void**)&p_Woh, g_Woh);
    cudaGetSymbolAddress((void**)&p_Wol, g_Wol);

    const int SMEM_T = 2 * (2 * (32 * 72 * 2) + 2 * (32 * 136 * 2));  // 53248
    const int SMEM_F = 2 * (2 * (64 * 40 * 2) + 2 * (32 * 136 * 2));  // 55296
    cudaFuncSetAttribute(mma_gemm<true, 0>,  cudaFuncAttributeMaxDynamicSharedMemorySize, SMEM_T);
    cudaFuncSetAttribute(mma_gemm<false, 1>, cudaFuncAttributeMaxDynamicSharedMemorySize, SMEM_F);
    cudaFuncSetAttribute(mma_gemm<false, 2>, cudaFuncAttributeMaxDynamicSharedMemorySize, SMEM_F);
    cudaFuncSetAttribute(mma_gemm<false, 3>, cudaFuncAttributeMaxDynamicSharedMemorySize, SMEM_F);

    const long M128 = (long)L_ * D_;        // 131072
    const long M1M  = (long)L_ * KE;        // 1048576

    // 1) tables + weight prep
    k_prep<<<202, 256>>>(bn_gamma, bn_beta, bn_mean, bn_var, log_Delta, Bp, Cp,
                         log_A, A_imag, W_in, b_in, W_out);
    // 2) fused rinv + E split
    k_erow<<<B_ * L_ / 8, 256>>>(EigVecs);
    // 3) x -> bn(x) bf16 split
    k_xcvt<<<(int)((long)B_ * L_ * D_ / 4 / 256), 256>>>(x);
    // 4) in-proj + gated act fused: u' (bf16 hi/lo)
    mma_gemm<false, 2><<<dim3(16, 8, 2), 256, SMEM_F>>>(
        p_xh, p_xl, p_Wih, p_Wil, nullptr, p_uh, p_ul, p_rinv, p_bp,
        4, 128, 256, M128, 0, M128);
    // 5) QTX[b][k][d] = sum_l E[l][k] * u'[l][d]
    mma_gemm<true, 0><<<dim3(16, 8, 1), 256, SMEM_T>>>(
        p_Eh, p_El, p_uh, p_ul, p_G, nullptr, nullptr, nullptr, nullptr,
        32, 1024, 128, M1M, M128, M128);
    // 6) G = QTX * W(b,k,d) -> bf16 hi/lo
    k_w<<<B_ * (KE / 64), D_>>>(EigVals);
    // 7) v = silu(rinv * E @ G) -> bf16 hi/lo
    mma_gemm<false, 1><<<dim3(16, 8, 1), 256, SMEM_F>>>(
        p_Eh, p_El, p_Gh, p_Gl, nullptr, p_vh, p_vl, p_rinv, nullptr,
        32, 1024, 128, M1M, M128, M128);
    // 8) y = v @ W_out + b_out
    mma_gemm<false, 3><<<dim3(16, 8, 1), 256, SMEM_F>>>(
        p_vh, p_vl, p_Woh, p_Wol, y, nullptr, nullptr, nullptr, b_out,
        4, 128, 128, M128, 0, M128);
}

// round 9
// speedup vs baseline: 1.9101x; 1.0904x over previous
#include <cuda_runtime.h>
#include <cuda_bf16.h>
#include <math.h>
#include <stdint.h>

// Problem constants
static constexpr int B_ = 8;
static constexpr int L_ = 1024;
static constexpr int KE = 1024;
static constexpr int D_ = 128;
static constexpr int S_ = 16;

// ---------------- scratch (device globals) ----------------------------------
__device__ float g_rinv[B_ * L_];
__device__ float g_G[(long)B_ * KE * D_];            // QTX fp32 [b][k][d]
__device__ __nv_bfloat16 g_Eh[(long)B_ * L_ * KE];
__device__ __nv_bfloat16 g_El[(long)B_ * L_ * KE];
__device__ __nv_bfloat16 g_xh[(long)B_ * L_ * D_];   // bn(x) hi/lo
__device__ __nv_bfloat16 g_xl[(long)B_ * L_ * D_];
__device__ __nv_bfloat16 g_uh[(long)B_ * L_ * D_];   // u' = x1*silu(z)*rinv
__device__ __nv_bfloat16 g_ul[(long)B_ * L_ * D_];
__device__ __nv_bfloat16 g_Gh[(long)B_ * KE * D_];
__device__ __nv_bfloat16 g_Gl[(long)B_ * KE * D_];
__device__ __nv_bfloat16 g_vh[(long)B_ * L_ * D_];   // silu(yssm)
__device__ __nv_bfloat16 g_vl[(long)B_ * L_ * D_];
__device__ __nv_bfloat16 g_Wih[D_ * 2 * D_];         // W_in packed (x1,z interleaved)
__device__ __nv_bfloat16 g_Wil[D_ * 2 * D_];
__device__ __nv_bfloat16 g_Woh[D_ * D_];
__device__ __nv_bfloat16 g_Wol[D_ * D_];
__device__ float g_bp[2 * D_];                       // b_in packed
__device__ float g_ar[D_ * S_];
__device__ float g_ai[D_ * S_];
__device__ float g_bc[D_ * S_];
__device__ float g_bns[D_];
__device__ float g_bnb[D_];

// ---------------- helpers ----------------------------------------------------
__device__ __forceinline__ uint32_t smem_u32(const void* p) {
    uint32_t a;
    asm("{ .reg .u64 t; cvta.to.shared.u64 t, %1; cvt.u32.u64 %0, t; }" : "=r"(a) : "l"(p));
    return a;
}
__device__ __forceinline__ void split2(float x, __nv_bfloat16& h, __nv_bfloat16& l) {
    h = __float2bfloat16_rn(x);
    l = __float2bfloat16_rn(x - __bfloat162float(h));
}

#define CP16(dst, src) \
    asm volatile("cp.async.ca.shared.global [%0], [%1], 16;" :: "r"(dst), "l"(src))
#define CP_COMMIT() asm volatile("cp.async.commit_group;" ::: "memory")
#define CP_WAIT(n)  asm volatile("cp.async.wait_group %0;" :: "n"(n) : "memory")

__device__ __forceinline__ void ldm_x4(uint32_t* r, uint32_t a) {
    asm volatile("ldmatrix.sync.aligned.m8n8.x4.shared.b16 {%0,%1,%2,%3}, [%4];"
        : "=r"(r[0]), "=r"(r[1]), "=r"(r[2]), "=r"(r[3]) : "r"(a));
}
__device__ __forceinline__ void ldm_x4t(uint32_t* r, uint32_t a) {
    asm volatile("ldmatrix.sync.aligned.m8n8.x4.trans.shared.b16 {%0,%1,%2,%3}, [%4];"
        : "=r"(r[0]), "=r"(r[1]), "=r"(r[2]), "=r"(r[3]) : "r"(a));
}
__device__ __forceinline__ void mma_bf16(float* c, const uint32_t* a, uint32_t b0, uint32_t b1) {
    asm volatile("mma.sync.aligned.m16n8k16.row.col.f32.bf16.bf16.f32 "
        "{%0,%1,%2,%3}, {%4,%5,%6,%7}, {%8,%9}, {%0,%1,%2,%3};"
        : "+f"(c[0]), "+f"(c[1]), "+f"(c[2]), "+f"(c[3])
        : "r"(a[0]), "r"(a[1]), "r"(a[2]), "r"(a[3]), "r"(b0), "r"(b1));
}
__device__ __forceinline__ float silu(float v) { return v / (1.f + expf(-v)); }
__device__ __forceinline__ uint32_t bf2u(__nv_bfloat162 v) {
    return *(uint32_t*)&v;
}

// ---------------- prep: SSM tables + BN fold + weight pack/split ------------
__global__ void k_prep(const float* __restrict__ gamma, const float* __restrict__ beta,
                       const float* __restrict__ mean,  const float* __restrict__ var,
                       const float* __restrict__ log_Delta,
                       const float* __restrict__ Bp,    const float* __restrict__ Cp,
                       const float* __restrict__ log_A_real,
                       const float* __restrict__ A_imag,
                       const float* __restrict__ W_in,  const float* __restrict__ b_in,
                       const float* __restrict__ W_out)
{
    int idx = blockIdx.x * blockDim.x + threadIdx.x;
    if (idx < 2048) {                    // D*S
        int d = idx / S_;
        float delta = expf(log_Delta[d]);
        float aRe = -expf(log_A_real[idx]);
        float aIm = A_imag[idx];
        float mag = expf(-1e-3f + delta * aRe);
        float sn, cs;
        sincosf(delta * aIm, &sn, &cs);
        g_ar[idx] = mag * cs;
        g_ai[idx] = mag * sn;
        g_bc[idx] = delta * Bp[idx] * Cp[idx];
    } else if (idx < 2048 + 128) {       // BN fold
        int d = idx - 2048;
        float sc = gamma[d] * rsqrtf(var[d] + 1e-5f);
        g_bns[d] = sc;
        g_bnb[d] = beta[d] - mean[d] * sc;
    } else if (idx < 2048 + 128 + 32768) {   // W_in pack + split
        int j = idx - (2048 + 128);
        int c = j >> 8, n = j & 255;
        int d = n >> 1, half = n & 1;
        float w = W_in[c * 256 + half * 128 + d];
        __nv_bfloat16 h, l;
        split2(w, h, l);
        g_Wih[j] = h; g_Wil[j] = l;
    } else if (idx < 2048 + 128 + 32768 + 16384) {  // W_out split
        int j = idx - (2048 + 128 + 32768);
        float w = W_out[j];
        __nv_bfloat16 h, l;
        split2(w, h, l);
        g_Woh[j] = h; g_Wol[j] = l;
    } else if (idx < 2048 + 128 + 32768 + 16384 + 256) {  // bias pack
        int j = idx - (2048 + 128 + 32768 + 16384);
        g_bp[j] = b_in[(j & 1) * 128 + (j >> 1)];
    }
}

// ---------------- fused: row inv-norm + E -> bf16 hi/lo ---------------------
__global__ void k_erow(const float* __restrict__ E)
{
    int row = blockIdx.x * 8 + (threadIdx.x >> 5);
    int lane = threadIdx.x & 31;
    const float4* p = (const float4*)(E + (long)row * KE);
    uint2* oh = (uint2*)(g_Eh + (long)row * KE);
    uint2* ol = (uint2*)(g_El + (long)row * KE);
    float s = 0.f;
#pragma unroll
    for (int i = 0; i < 8; i++) {
        int c4 = lane + i * 32;                 // float4 index
        float4 v = p[c4];
        s += v.x * v.x + v.y * v.y + v.z * v.z + v.w * v.w;
        __nv_bfloat162 h01, h23, l01, l23;
        h01.x = __float2bfloat16_rn(v.x); l01.x = __float2bfloat16_rn(v.x - __bfloat162float(h01.x));
        h01.y = __float2bfloat16_rn(v.y); l01.y = __float2bfloat16_rn(v.y - __bfloat162float(h01.y));
        h23.x = __float2bfloat16_rn(v.z); l23.x = __float2bfloat16_rn(v.z - __bfloat162float(h23.x));
        h23.y = __float2bfloat16_rn(v.w); l23.y = __float2bfloat16_rn(v.w - __bfloat162float(h23.y));
        oh[c4] = make_uint2(bf2u(h01), bf2u(h23));
        ol[c4] = make_uint2(bf2u(l01), bf2u(l23));
    }
#pragma unroll
    for (int o = 16; o; o >>= 1) s += __shfl_xor_sync(0xffffffffu, s, o);
    if (lane == 0) g_rinv[row] = (s > 0.f) ? (1.0f / sqrtf(s)) : 0.f;
}

// ---------------- x -> bn(x) bf16 hi/lo --------------------------------------
__global__ void k_xcvt(const float* __restrict__ x)
{
    long i = (long)blockIdx.x * 256 + threadIdx.x;   // float4 index
    int c = ((int)i & 31) * 4;
    float4 v = ((const float4*)x)[i];
    v.x = v.x * g_bns[c + 0] + g_bnb[c + 0];
    v.y = v.y * g_bns[c + 1] + g_bnb[c + 1];
    v.z = v.z * g_bns[c + 2] + g_bnb[c + 2];
    v.w = v.w * g_bns[c + 3] + g_bnb[c + 3];
    __nv_bfloat162 h01, h23, l01, l23;
    h01.x = __float2bfloat16_rn(v.x); l01.x = __float2bfloat16_rn(v.x - __bfloat162float(h01.x));
    h01.y = __float2bfloat16_rn(v.y); l01.y = __float2bfloat16_rn(v.y - __bfloat162float(h01.y));
    h23.x = __float2bfloat16_rn(v.z); l23.x = __float2bfloat16_rn(v.z - __bfloat162float(h23.x));
    h23.y = __float2bfloat16_rn(v.w); l23.y = __float2bfloat16_rn(v.w - __bfloat162float(h23.y));
    ((uint2*)g_xh)[i] = make_uint2(bf2u(h01), bf2u(h23));
    ((uint2*)g_xl)[i] = make_uint2(bf2u(l01), bf2u(l23));
}

// ---------------- SSM weight: G = QTX * W(b,k,d) -> bf16 hi/lo ---------------
__global__ void k_w(const float* __restrict__ EigVals)
{
    int blk = blockIdx.x;
    int b  = blk >> 4;
    int k0 = (blk & 15) << 6;
    int d  = threadIdx.x;
    float lar[S_], lm2[S_], lbc[S_];
#pragma unroll
    for (int s = 0; s < S_; s++) {
        float ar = g_ar[d * S_ + s], ai = g_ai[d * S_ + s];
        lar[s] = ar;
        lm2[s] = ar * ar + ai * ai;
        lbc[s] = g_bc[d * S_ + s];
    }
#pragma unroll 4
    for (int kk = 0; kk < 64; kk++) {
        int k = k0 + kk;
        float e = 1.0f - __ldg(&EigVals[b * KE + k]);
        float e2 = e * e;
        float acc = 0.f;
#pragma unroll
        for (int s = 0; s < S_; s++) {
            float t1 = e * lar[s];
            float t2 = e2 * lm2[s];
            // num = Re(lamA*conj(1-lamA)) = t1 - t2 ; den = |1-lamA|^2 = 1 - 2t1 + t2
            acc += __fdividef(t1 - t2, 1.f - 2.f * t1 + t2) * lbc[s];
        }
        long gi = ((long)(b * KE + k)) * D_ + d;
        float val = g_G[gi] * acc;
        __nv_bfloat16 h, l;
        split2(val, h, l);
        g_Gh[gi] = h;
        g_Gl[gi] = l;
    }
}

// ---------------- split-bf16 HMMA GEMM (4-stage cp.async pipeline) -----------
// Per batch b (blockIdx.y): C[m][n] = sum_c opA[m][c] * B[c][n]
// CTA tile 64(M) x 128(N); n0 = blockIdx.z*128 (B col offset).
// EPI 0: fp32 store | 1: silu(rinv*acc)->bf16 hi/lo | 2: gated pair -> bf16 hi/lo
// EPI 3: acc + bias -> fp32
template <bool TRANSA, int EPI>
__global__ __launch_bounds__(256, 1)
void mma_gemm(const __nv_bfloat16* __restrict__ Ah, const __nv_bfloat16* __restrict__ Al,
              const __nv_bfloat16* __restrict__ Bh, const __nv_bfloat16* __restrict__ Bl,
              float* __restrict__ Cf, __nv_bfloat16* __restrict__ Ch, __nv_bfloat16* __restrict__ Cl,
              const float* __restrict__ rinv, const float* __restrict__ bias,
              int nch, int lda, int ldb, long aStr, long bStr, long cStr)
{
    constexpr int A_SZ  = TRANSA ? 32 * 72 * 2 : 64 * 40 * 2;
    constexpr int ASTRB = TRANSA ? 144 : 80;
    constexpr int B_SZ  = 32 * 136 * 2;
    constexpr int BSTRB = 272;
    constexpr int STAGE = 2 * A_SZ + 2 * B_SZ;

    extern __shared__ char smem[];
    const uint32_t sb = smem_u32(smem);

    const int tid  = threadIdx.x;
    const int lane = tid & 31;
    const int wid  = tid >> 5;
    const int m_w  = (wid & 1) * 32;
    const int n_w  = (wid >> 1) * 32;
    const int b    = blockIdx.y;
    const int m0   = blockIdx.x * 64;
    const int n0   = blockIdx.z * 128;

    const int ar = TRANSA ? (tid >> 3) : (tid >> 2);
    const int ac = TRANSA ? (tid & 7)  : (tid & 3);

    float acc[2][4][4];
#pragma unroll
    for (int i = 0; i < 2; i++)
#pragma unroll
        for (int j = 0; j < 4; j++)
#pragma unroll
            for (int q = 0; q < 4; q++) acc[i][j][q] = 0.f;

    auto issue_chunk = [&](int ch) {
        const uint32_t st = sb + (uint32_t)(ch & 3) * STAGE;
        long g;
        if (TRANSA) g = (long)b * aStr + (long)(ch * 32 + ar) * lda + m0 + ac * 8;
        else        g = (long)b * aStr + (long)(m0 + ar) * lda + ch * 32 + ac * 8;
        uint32_t dst = st + ar * ASTRB + ac * 16;
        CP16(dst,        Ah + g);
        CP16(dst + A_SZ, Al + g);
#pragma unroll
        for (int q = 0; q < 2; q++) {
            int idx = tid + q * 256;
            int row = idx >> 4, c4 = idx & 15;
            long gb = (long)b * bStr + (long)(ch * 32 + row) * ldb + n0 + c4 * 8;
            uint32_t d2 = st + 2 * A_SZ + row * BSTRB + c4 * 16;
            CP16(d2,        Bh + gb);
            CP16(d2 + B_SZ, Bl + gb);
        }
        CP_COMMIT();
    };

    // prologue: 3 chunks in flight
    issue_chunk(0);
    issue_chunk(1);
    issue_chunk(2);

    for (int ch = 0; ch < nch; ++ch) {
        CP_WAIT(2);            // chunk ch complete (3 groups always pending)
        __syncthreads();       // all copies visible; stage (ch-1)&3 free for reuse
        if (ch + 3 < nch) issue_chunk(ch + 3);
        else              CP_COMMIT();   // empty group keeps the wait count exact

        const uint32_t st = sb + (uint32_t)(ch & 3) * STAGE;
        const uint32_t aOff = st;
        const uint32_t bOff = st + 2 * A_SZ;

        uint32_t ah[2][2][4], al[2][2][4];
#pragma unroll
        for (int mi = 0; mi < 2; mi++)
#pragma unroll
            for (int kk = 0; kk < 2; kk++) {
                uint32_t addr;
                if (TRANSA) {
                    int g = lane >> 3, r = lane & 7;
                    int row = kk * 16 + ((g & 2) ? 8 : 0) + r;
                    int col = m_w + mi * 16 + ((g & 1) ? 8 : 0);
                    addr = aOff + row * ASTRB + col * 2;
                    ldm_x4t(ah[mi][kk], addr);
                    ldm_x4t(al[mi][kk], addr + A_SZ);
                } else {
                    int row = m_w + mi * 16 + (lane & 15);
                    int col = kk * 16 + (lane >> 4) * 8;
                    addr = aOff + row * ASTRB + col * 2;
                    ldm_x4(ah[mi][kk], addr);
                    ldm_x4(al[mi][kk], addr + A_SZ);
                }
            }
        uint32_t bh[2][2][4], bl[2][2][4];
#pragma unroll
        for (int bi = 0; bi < 2; bi++)
#pragma unroll
            for (int kk = 0; kk < 2; kk++) {
                int g = lane >> 3, r = lane & 7;
                int row = kk * 16 + ((g & 2) ? 8 : 0) + r;
                int col = n_w + bi * 16 + ((g & 1) ? 8 : 0);
                uint32_t addr = bOff + row * BSTRB + col * 2;
                ldm_x4t(bh[bi][kk], addr);
                ldm_x4t(bl[bi][kk], addr + B_SZ);
            }

#pragma unroll
        for (int mi = 0; mi < 2; mi++)
#pragma unroll
            for (int bi = 0; bi < 2; bi++)
#pragma unroll
                for (int sub = 0; sub < 2; sub++) {
                    float* c = acc[mi][bi * 2 + sub];
#pragma unroll
                    for (int kk = 0; kk < 2; kk++) {
                        uint32_t bh0 = bh[bi][kk][sub], bh1 = bh[bi][kk][sub + 2];
                        uint32_t bl0 = bl[bi][kk][sub], bl1 = bl[bi][kk][sub + 2];
                        mma_bf16(c, ah[mi][kk], bh0, bh1);
                        mma_bf16(c, al[mi][kk], bh0, bh1);
                        mma_bf16(c, ah[mi][kk], bl0, bl1);
                    }
                }
    }

    // ---- epilogue ----
#pragma unroll
    for (int mi = 0; mi < 2; mi++) {
        int r0 = m0 + m_w + mi * 16 + (lane >> 2);
        int r1 = r0 + 8;
        float rs0 = 1.f, rs1 = 1.f;
        if (EPI == 1 || EPI == 2) {
            rs0 = rinv[b * 1024 + r0];
            rs1 = rinv[b * 1024 + r1];
        }
#pragma unroll
        for (int ni = 0; ni < 4; ni++) {
            int col = n_w + ni * 8 + (lane & 3) * 2;
            float v0 = acc[mi][ni][0], v1 = acc[mi][ni][1];
            float v2 = acc[mi][ni][2], v3 = acc[mi][ni][3];
            if (EPI == 0) {
                *(float2*)(Cf + (long)b * cStr + (long)r0 * 128 + col) = make_float2(v0, v1);
                *(float2*)(Cf + (long)b * cStr + (long)r1 * 128 + col) = make_float2(v2, v3);
            } else if (EPI == 3) {
                float b0 = bias[col], b1 = bias[col + 1];
                *(float2*)(Cf + (long)b * cStr + (long)r0 * 128 + col) = make_float2(v0 + b0, v1 + b1);
                *(float2*)(Cf + (long)b * cStr + (long)r1 * 128 + col) = make_float2(v2 + b0, v3 + b1);
            } else if (EPI == 1) {
                v0 = silu(v0 * rs0); v1 = silu(v1 * rs0);
                v2 = silu(v2 * rs1); v3 = silu(v3 * rs1);
                __nv_bfloat16 h, l;
                __nv_bfloat162 h01, l01, h23, l23;
                split2(v0, h, l); h01.x = h; l01.x = l;
                split2(v1, h, l); h01.y = h; l01.y = l;
                split2(v2, h, l); h23.x = h; l23.x = l;
                split2(v3, h, l); h23.y = h; l23.y = l;
                long o0 = (long)b * cStr + (long)r0 * 128 + col;
                long o1 = (long)b * cStr + (long)r1 * 128 + col;
                *(__nv_bfloat162*)(Ch + o0) = h01;
                *(__nv_bfloat162*)(Cl + o0) = l01;
                *(__nv_bfloat162*)(Ch + o1) = h23;
                *(__nv_bfloat162*)(Cl + o1) = l23;
            } else {  // EPI == 2 gated
                float bx = bias[n0 + col], bz = bias[n0 + col + 1];
                float u0 = (v0 + bx) * silu(v1 + bz) * rs0;
                float u1 = (v2 + bx) * silu(v3 + bz) * rs1;
                int dcol = blockIdx.z * 64 + (col >> 1);
                __nv_bfloat16 h0, l0, h1, l1;
                split2(u0, h0, l0);
                split2(u1, h1, l1);
                long o0 = (long)b * cStr + (long)r0 * 128 + dcol;
                long o1 = (long)b * cStr + (long)r1 * 128 + dcol;
                Ch[o0] = h0; Cl[o0] = l0;
                Ch[o1] = h1; Cl[o1] = l1;
            }
        }
    }
}

// ---------------- launch ----------------------------------------------------
extern "C" void kernel_launch(void* const* d_in, const int* in_sizes, int n_in,
                              void* d_out, int out_size)
{
    const float* x        = (const float*)d_in[0];
    const float* EigVecs  = (const float*)d_in[2];
    const float* EigVals  = (const float*)d_in[3];
    const float* bn_gamma = (const float*)d_in[4];
    const float* bn_beta  = (const float*)d_in[5];
    const float* bn_mean  = (const float*)d_in[6];
    const float* bn_var   = (const float*)d_in[7];
    const float* W_in     = (const float*)d_in[8];
    const float* b_in     = (const float*)d_in[9];
    const float* log_Delta= (const float*)d_in[10];
    const float* Bp       = (const float*)d_in[11];
    const float* Cp       = (const float*)d_in[12];
    const float* log_A    = (const float*)d_in[13];
    const float* A_imag   = (const float*)d_in[14];
    const float* W_out    = (const float*)d_in[15];
    const float* b_out    = (const float*)d_in[16];
    float* y = (float*)d_out;

    float *p_G, *p_rinv, *p_bp;
    __nv_bfloat16 *p_Eh, *p_El, *p_xh, *p_xl, *p_uh, *p_ul, *p_Gh, *p_Gl, *p_vh, *p_vl;
    __nv_bfloat16 *p_Wih, *p_Wil, *p_Woh, *p_Wol;
    cudaGetSymbolAddress((void**)&p_G, g_G);
    cudaGetSymbolAddress((void**)&p_rinv, g_rinv);
    cudaGetSymbolAddress((void**)&p_bp, g_bp);
    cudaGetSymbolAddress((void**)&p_Eh, g_Eh);
    cudaGetSymbolAddress((void**)&p_El, g_El);
    cudaGetSymbolAddress((void**)&p_xh, g_xh);
    cudaGetSymbolAddress((void**)&p_xl, g_xl);
    cudaGetSymbolAddress((void**)&p_uh, g_uh);
    cudaGetSymbolAddress((void**)&p_ul, g_ul);
    cudaGetSymbolAddress((void**)&p_Gh, g_Gh);
    cudaGetSymbolAddress((void**)&p_Gl, g_Gl);
    cudaGetSymbolAddress((void**)&p_vh, g_vh);
    cudaGetSymbolAddress((void**)&p_vl, g_vl);
    cudaGetSymbolAddress((void**)&p_Wih, g_Wih);
    cudaGetSymbolAddress((void**)&p_Wil, g_Wil);
    cudaGetSymbolAddress((void**)&p_Woh, g_Woh);
    cudaGetSymbolAddress((void**)&p_Wol, g_Wol);

    // 4-stage smem
    const int SMEM_T = 4 * (2 * (32 * 72 * 2) + 2 * (32 * 136 * 2));  // 106496
    const int SMEM_F = 4 * (2 * (64 * 40 * 2) + 2 * (32 * 136 * 2));  // 110592
    cudaFuncSetAttribute(mma_gemm<true, 0>,  cudaFuncAttributeMaxDynamicSharedMemorySize, SMEM_T);
    cudaFuncSetAttribute(mma_gemm<false, 1>, cudaFuncAttributeMaxDynamicSharedMemorySize, SMEM_F);
    cudaFuncSetAttribute(mma_gemm<false, 2>, cudaFuncAttributeMaxDynamicSharedMemorySize, SMEM_F);
    cudaFuncSetAttribute(mma_gemm<false, 3>, cudaFuncAttributeMaxDynamicSharedMemorySize, SMEM_F);

    const long M128 = (long)L_ * D_;        // 131072
    const long M1M  = (long)L_ * KE;        // 1048576

    // 1) tables + weight prep
    k_prep<<<202, 256>>>(bn_gamma, bn_beta, bn_mean, bn_var, log_Delta, Bp, Cp,
                         log_A, A_imag, W_in, b_in, W_out);
    // 2) fused rinv + E split
    k_erow<<<B_ * L_ / 8, 256>>>(EigVecs);
    // 3) x -> bn(x) bf16 split
    k_xcvt<<<(int)((long)B_ * L_ * D_ / 4 / 256), 256>>>(x);
    // 4) in-proj + gated act fused: u' (bf16 hi/lo)
    mma_gemm<false, 2><<<dim3(16, 8, 2), 256, SMEM_F>>>(
        p_xh, p_xl, p_Wih, p_Wil, nullptr, p_uh, p_ul, p_rinv, p_bp,
        4, 128, 256, M128, 0, M128);
    // 5) QTX[b][k][d] = sum_l E[l][k] * u'[l][d]
    mma_gemm<true, 0><<<dim3(16, 8, 1), 256, SMEM_T>>>(
        p_Eh, p_El, p_uh, p_ul, p_G, nullptr, nullptr, nullptr, nullptr,
        32, 1024, 128, M1M, M128, M128);
    // 6) G = QTX * W(b,k,d) -> bf16 hi/lo
    k_w<<<B_ * (KE / 64), D_>>>(EigVals);
    // 7) v = silu(rinv * E @ G) -> bf16 hi/lo
    mma_gemm<false, 1><<<dim3(16, 8, 1), 256, SMEM_F>>>(
        p_Eh, p_El, p_Gh, p_Gl, nullptr, p_vh, p_vl, p_rinv, nullptr,
        32, 1024, 128, M1M, M128, M128);
    // 8) y = v @ W_out + b_out
    mma_gemm<false, 3><<<dim3(16, 8, 1), 256, SMEM_F>>>(
        p_vh, p_vl, p_Woh, p_Wol, y, nullptr, nullptr, nullptr, b_out,
        4, 128, 128, M128, 0, M128);
}

// round 10
// speedup vs baseline: 2.1080x; 1.1036x over previous
#include <cuda_runtime.h>
#include <cuda_bf16.h>
#include <math.h>
#include <stdint.h>

// Problem constants
static constexpr int B_ = 8;
static constexpr int L_ = 1024;
static constexpr int KE = 1024;
static constexpr int D_ = 128;
static constexpr int S_ = 16;

// ---------------- scratch (device globals) ----------------------------------
__device__ float g_rinv[B_ * L_];
__device__ __nv_bfloat16 g_Eh[(long)B_ * L_ * KE];
__device__ __nv_bfloat16 g_El[(long)B_ * L_ * KE];
__device__ __nv_bfloat16 g_xh[(long)B_ * L_ * D_];   // bn(x) hi/lo
__device__ __nv_bfloat16 g_xl[(long)B_ * L_ * D_];
__device__ __nv_bfloat16 g_uh[(long)B_ * L_ * D_];   // u' = x1*silu(z)*rinv
__device__ __nv_bfloat16 g_ul[(long)B_ * L_ * D_];
__device__ __nv_bfloat16 g_Gh[(long)B_ * KE * D_];   // G = QTX * W
__device__ __nv_bfloat16 g_Gl[(long)B_ * KE * D_];
__device__ __nv_bfloat16 g_vh[(long)B_ * L_ * D_];   // silu(yssm)
__device__ __nv_bfloat16 g_vl[(long)B_ * L_ * D_];
__device__ __nv_bfloat16 g_Wih[D_ * 2 * D_];         // W_in packed (x1,z interleaved)
__device__ __nv_bfloat16 g_Wil[D_ * 2 * D_];
__device__ __nv_bfloat16 g_Woh[D_ * D_];
__device__ __nv_bfloat16 g_Wol[D_ * D_];
__device__ float g_bp[2 * D_];                       // b_in packed
__device__ float g_ar[D_ * S_];                      // Re(Abar)
__device__ float g_m2[D_ * S_];                      // |Abar|^2
__device__ float g_bc[D_ * S_];                      // delta*Bp*Cp
__device__ float g_bns[D_];
__device__ float g_bnb[D_];

// ---------------- helpers ----------------------------------------------------
__device__ __forceinline__ uint32_t smem_u32(const void* p) {
    uint32_t a;
    asm("{ .reg .u64 t; cvta.to.shared.u64 t, %1; cvt.u32.u64 %0, t; }" : "=r"(a) : "l"(p));
    return a;
}
__device__ __forceinline__ void split2(float x, __nv_bfloat16& h, __nv_bfloat16& l) {
    h = __float2bfloat16_rn(x);
    l = __float2bfloat16_rn(x - __bfloat162float(h));
}

#define CP16(dst, src) \
    asm volatile("cp.async.ca.shared.global [%0], [%1], 16;" :: "r"(dst), "l"(src))
#define CP_COMMIT() asm volatile("cp.async.commit_group;" ::: "memory")
#define CP_WAIT(n)  asm volatile("cp.async.wait_group %0;" :: "n"(n) : "memory")

__device__ __forceinline__ void ldm_x4(uint32_t* r, uint32_t a) {
    asm volatile("ldmatrix.sync.aligned.m8n8.x4.shared.b16 {%0,%1,%2,%3}, [%4];"
        : "=r"(r[0]), "=r"(r[1]), "=r"(r[2]), "=r"(r[3]) : "r"(a));
}
__device__ __forceinline__ void ldm_x4t(uint32_t* r, uint32_t a) {
    asm volatile("ldmatrix.sync.aligned.m8n8.x4.trans.shared.b16 {%0,%1,%2,%3}, [%4];"
        : "=r"(r[0]), "=r"(r[1]), "=r"(r[2]), "=r"(r[3]) : "r"(a));
}
__device__ __forceinline__ void mma_bf16(float* c, const uint32_t* a, uint32_t b0, uint32_t b1) {
    asm volatile("mma.sync.aligned.m16n8k16.row.col.f32.bf16.bf16.f32 "
        "{%0,%1,%2,%3}, {%4,%5,%6,%7}, {%8,%9}, {%0,%1,%2,%3};"
        : "+f"(c[0]), "+f"(c[1]), "+f"(c[2]), "+f"(c[3])
        : "r"(a[0]), "r"(a[1]), "r"(a[2]), "r"(a[3]), "r"(b0), "r"(b1));
}
__device__ __forceinline__ float silu(float v) { return v / (1.f + expf(-v)); }
__device__ __forceinline__ uint32_t bf2u(__nv_bfloat162 v) { return *(uint32_t*)&v; }

// ---------------- prep: SSM tables + BN fold + weight pack/split ------------
__global__ void k_prep(const float* __restrict__ gamma, const float* __restrict__ beta,
                       const float* __restrict__ mean,  const float* __restrict__ var,
                       const float* __restrict__ log_Delta,
                       const float* __restrict__ Bp,    const float* __restrict__ Cp,
                       const float* __restrict__ log_A_real,
                       const float* __restrict__ A_imag,
                       const float* __restrict__ W_in,  const float* __restrict__ b_in,
                       const float* __restrict__ W_out)
{
    int idx = blockIdx.x * blockDim.x + threadIdx.x;
    if (idx < 2048) {                    // D*S
        int d = idx / S_;
        float delta = expf(log_Delta[d]);
        float aRe = -expf(log_A_real[idx]);
        float aIm = A_imag[idx];
        float mag = expf(-1e-3f + delta * aRe);
        float sn, cs;
        sincosf(delta * aIm, &sn, &cs);
        float ar = mag * cs, ai = mag * sn;
        g_ar[idx] = ar;
        g_m2[idx] = ar * ar + ai * ai;
        g_bc[idx] = delta * Bp[idx] * Cp[idx];
    } else if (idx < 2048 + 128) {       // BN fold
        int d = idx - 2048;
        float sc = gamma[d] * rsqrtf(var[d] + 1e-5f);
        g_bns[d] = sc;
        g_bnb[d] = beta[d] - mean[d] * sc;
    } else if (idx < 2048 + 128 + 32768) {   // W_in pack + split
        int j = idx - (2048 + 128);
        int c = j >> 8, n = j & 255;
        int d = n >> 1, half = n & 1;
        float w = W_in[c * 256 + half * 128 + d];
        __nv_bfloat16 h, l;
        split2(w, h, l);
        g_Wih[j] = h; g_Wil[j] = l;
    } else if (idx < 2048 + 128 + 32768 + 16384) {  // W_out split
        int j = idx - (2048 + 128 + 32768);
        float w = W_out[j];
        __nv_bfloat16 h, l;
        split2(w, h, l);
        g_Woh[j] = h; g_Wol[j] = l;
    } else if (idx < 2048 + 128 + 32768 + 16384 + 256) {  // bias pack
        int j = idx - (2048 + 128 + 32768 + 16384);
        g_bp[j] = b_in[(j & 1) * 128 + (j >> 1)];
    }
}

// ---------------- fused: row inv-norm + E -> bf16 hi/lo ---------------------
__global__ void k_erow(const float* __restrict__ E)
{
    int row = blockIdx.x * 8 + (threadIdx.x >> 5);
    int lane = threadIdx.x & 31;
    const float4* p = (const float4*)(E + (long)row * KE);
    uint2* oh = (uint2*)(g_Eh + (long)row * KE);
    uint2* ol = (uint2*)(g_El + (long)row * KE);
    float s = 0.f;
#pragma unroll
    for (int i = 0; i < 8; i++) {
        int c4 = lane + i * 32;
        float4 v = p[c4];
        s += v.x * v.x + v.y * v.y + v.z * v.z + v.w * v.w;
        __nv_bfloat162 h01, h23, l01, l23;
        h01.x = __float2bfloat16_rn(v.x); l01.x = __float2bfloat16_rn(v.x - __bfloat162float(h01.x));
        h01.y = __float2bfloat16_rn(v.y); l01.y = __float2bfloat16_rn(v.y - __bfloat162float(h01.y));
        h23.x = __float2bfloat16_rn(v.z); l23.x = __float2bfloat16_rn(v.z - __bfloat162float(h23.x));
        h23.y = __float2bfloat16_rn(v.w); l23.y = __float2bfloat16_rn(v.w - __bfloat162float(h23.y));
        oh[c4] = make_uint2(bf2u(h01), bf2u(h23));
        ol[c4] = make_uint2(bf2u(l01), bf2u(l23));
    }
#pragma unroll
    for (int o = 16; o; o >>= 1) s += __shfl_xor_sync(0xffffffffu, s, o);
    if (lane == 0) g_rinv[row] = (s > 0.f) ? (1.0f / sqrtf(s)) : 0.f;
}

// ---------------- x -> bn(x) bf16 hi/lo --------------------------------------
__global__ void k_xcvt(const float* __restrict__ x)
{
    long i = (long)blockIdx.x * 256 + threadIdx.x;
    int c = ((int)i & 31) * 4;
    float4 v = ((const float4*)x)[i];
    v.x = v.x * g_bns[c + 0] + g_bnb[c + 0];
    v.y = v.y * g_bns[c + 1] + g_bnb[c + 1];
    v.z = v.z * g_bns[c + 2] + g_bnb[c + 2];
    v.w = v.w * g_bns[c + 3] + g_bnb[c + 3];
    __nv_bfloat162 h01, h23, l01, l23;
    h01.x = __float2bfloat16_rn(v.x); l01.x = __float2bfloat16_rn(v.x - __bfloat162float(h01.x));
    h01.y = __float2bfloat16_rn(v.y); l01.y = __float2bfloat16_rn(v.y - __bfloat162float(h01.y));
    h23.x = __float2bfloat16_rn(v.z); l23.x = __float2bfloat16_rn(v.z - __bfloat162float(h23.x));
    h23.y = __float2bfloat16_rn(v.w); l23.y = __float2bfloat16_rn(v.w - __bfloat162float(h23.y));
    ((uint2*)g_xh)[i] = make_uint2(bf2u(h01), bf2u(h23));
    ((uint2*)g_xl)[i] = make_uint2(bf2u(l01), bf2u(l23));
}

// ---------------- split-bf16 HMMA GEMM, 32x128 tile, 4 warps, 4 stages -------
// Per batch b (blockIdx.y): C[m][n] = sum_c opA[m][c] * B[c][n]
// EPI 1: silu(rinv*acc)->bf16 hi/lo | EPI 2: gated pair -> bf16 hi/lo
// EPI 3: acc + bias -> fp32        | EPI 4: fused SSM weight -> bf16 hi/lo (G)
//   (EPI 4: `bias` carries EigVals)
template <bool TRANSA, int EPI>
__global__ __launch_bounds__(128)
void mma_gemm(const __nv_bfloat16* __restrict__ Ah, const __nv_bfloat16* __restrict__ Al,
              const __nv_bfloat16* __restrict__ Bh, const __nv_bfloat16* __restrict__ Bl,
              float* __restrict__ Cf, __nv_bfloat16* __restrict__ Ch, __nv_bfloat16* __restrict__ Cl,
              const float* __restrict__ rinv, const float* __restrict__ bias,
              int nch, int lda, int ldb, long aStr, long bStr, long cStr)
{
    constexpr int A_SZ  = 32 * 80;        // 32 rows x (64B data + 16B pad)
    constexpr int ASTRB = 80;
    constexpr int B_SZ  = 32 * 272;       // 32 rows x (256B data + 16B pad)
    constexpr int BSTRB = 272;
    constexpr int STAGE = 2 * A_SZ + 2 * B_SZ;   // 22528

    extern __shared__ char smem[];
    const uint32_t sb = smem_u32(smem);

    const int tid  = threadIdx.x;
    const int lane = tid & 31;
    const int wid  = tid >> 5;
    const int n_w  = wid * 32;
    const int b    = blockIdx.y;
    const int m0   = blockIdx.x * 32;
    const int n0   = blockIdx.z * 128;

    const int arow = tid >> 2;      // 0..31
    const int acol = tid & 3;       // 16B col

    float acc[2][4][4];
#pragma unroll
    for (int i = 0; i < 2; i++)
#pragma unroll
        for (int j = 0; j < 4; j++)
#pragma unroll
            for (int q = 0; q < 4; q++) acc[i][j][q] = 0.f;

    auto issue_chunk = [&](int ch) {
        const uint32_t st = sb + (uint32_t)(ch & 3) * STAGE;
        long g;
        if (TRANSA) g = (long)b * aStr + (long)(ch * 32 + arow) * lda + m0 + acol * 8;
        else        g = (long)b * aStr + (long)(m0 + arow) * lda + ch * 32 + acol * 8;
        uint32_t dst = st + arow * ASTRB + acol * 16;
        CP16(dst,        Ah + g);
        CP16(dst + A_SZ, Al + g);
#pragma unroll
        for (int q = 0; q < 4; q++) {
            int idx = tid + q * 128;
            int row = idx >> 4, c4 = idx & 15;
            long gb = (long)b * bStr + (long)(ch * 32 + row) * ldb + n0 + c4 * 8;
            uint32_t d2 = st + 2 * A_SZ + row * BSTRB + c4 * 16;
            CP16(d2,        Bh + gb);
            CP16(d2 + B_SZ, Bl + gb);
        }
        CP_COMMIT();
    };

    issue_chunk(0);
    issue_chunk(1);
    issue_chunk(2);

    for (int ch = 0; ch < nch; ++ch) {
        CP_WAIT(2);
        __syncthreads();
        if (ch + 3 < nch) issue_chunk(ch + 3);
        else              CP_COMMIT();

        const uint32_t st = sb + (uint32_t)(ch & 3) * STAGE;
        const uint32_t aOff = st;
        const uint32_t bOff = st + 2 * A_SZ;

        uint32_t ah[2][2][4], al[2][2][4];
#pragma unroll
        for (int mi = 0; mi < 2; mi++)
#pragma unroll
            for (int kk = 0; kk < 2; kk++) {
                uint32_t addr;
                if (TRANSA) {
                    int g = lane >> 3, r = lane & 7;
                    int row = kk * 16 + ((g & 2) ? 8 : 0) + r;
                    int col = mi * 16 + ((g & 1) ? 8 : 0);
                    addr = aOff + row * ASTRB + col * 2;
                    ldm_x4t(ah[mi][kk], addr);
                    ldm_x4t(al[mi][kk], addr + A_SZ);
                } else {
                    int row = mi * 16 + (lane & 15);
                    int col = kk * 16 + (lane >> 4) * 8;
                    addr = aOff + row * ASTRB + col * 2;
                    ldm_x4(ah[mi][kk], addr);
                    ldm_x4(al[mi][kk], addr + A_SZ);
                }
            }
        uint32_t bh[2][2][4], bl[2][2][4];
#pragma unroll
        for (int bi = 0; bi < 2; bi++)
#pragma unroll
            for (int kk = 0; kk < 2; kk++) {
                int g = lane >> 3, r = lane & 7;
                int row = kk * 16 + ((g & 2) ? 8 : 0) + r;
                int col = n_w + bi * 16 + ((g & 1) ? 8 : 0);
                uint32_t addr = bOff + row * BSTRB + col * 2;
                ldm_x4t(bh[bi][kk], addr);
                ldm_x4t(bl[bi][kk], addr + B_SZ);
            }

#pragma unroll
        for (int mi = 0; mi < 2; mi++)
#pragma unroll
            for (int bi = 0; bi < 2; bi++)
#pragma unroll
                for (int sub = 0; sub < 2; sub++) {
                    float* c = acc[mi][bi * 2 + sub];
#pragma unroll
                    for (int kk = 0; kk < 2; kk++) {
                        uint32_t bh0 = bh[bi][kk][sub], bh1 = bh[bi][kk][sub + 2];
                        uint32_t bl0 = bl[bi][kk][sub], bl1 = bl[bi][kk][sub + 2];
                        mma_bf16(c, ah[mi][kk], bh0, bh1);
                        mma_bf16(c, al[mi][kk], bh0, bh1);
                        mma_bf16(c, ah[mi][kk], bl0, bl1);
                    }
                }
    }

    // ---- fused SSM weights (EPI 4): w[e-row][d-col], tables read once -------
    float w[4][8];
    if (EPI == 4) {
        float ee[4], ee2[4];
#pragma unroll
        for (int mi = 0; mi < 2; mi++) {
            int r = m0 + mi * 16 + (lane >> 2);
            ee[mi * 2 + 0] = 1.0f - bias[b * 1024 + r];
            ee[mi * 2 + 1] = 1.0f - bias[b * 1024 + r + 8];
        }
#pragma unroll
        for (int q = 0; q < 4; q++) ee2[q] = ee[q] * ee[q];
#pragma unroll
        for (int j = 0; j < 8; j++) {
            int d = n_w + (j >> 1) * 8 + (lane & 3) * 2 + (j & 1);
            const float* par = g_ar + d * S_;
            const float* pm2 = g_m2 + d * S_;
            const float* pbc = g_bc + d * S_;
            float w0 = 0.f, w1 = 0.f, w2 = 0.f, w3 = 0.f;
#pragma unroll
            for (int s = 0; s < S_; s++) {
                float ar = par[s], m2 = pm2[s], bc = pbc[s];
                float t1, t2;
                t1 = ee[0] * ar; t2 = ee2[0] * m2;
                w0 += __fdividef(t1 - t2, 1.f - 2.f * t1 + t2) * bc;
                t1 = ee[1] * ar; t2 = ee2[1] * m2;
                w1 += __fdividef(t1 - t2, 1.f - 2.f * t1 + t2) * bc;
                t1 = ee[2] * ar; t2 = ee2[2] * m2;
                w2 += __fdividef(t1 - t2, 1.f - 2.f * t1 + t2) * bc;
                t1 = ee[3] * ar; t2 = ee2[3] * m2;
                w3 += __fdividef(t1 - t2, 1.f - 2.f * t1 + t2) * bc;
            }
            w[0][j] = w0; w[1][j] = w1; w[2][j] = w2; w[3][j] = w3;
        }
    }

    // ---- epilogue ----
#pragma unroll
    for (int mi = 0; mi < 2; mi++) {
        int r0 = m0 + mi * 16 + (lane >> 2);
        int r1 = r0 + 8;
        float rs0 = 1.f, rs1 = 1.f;
        if (EPI == 1 || EPI == 2) {
            rs0 = rinv[b * 1024 + r0];
            rs1 = rinv[b * 1024 + r1];
        }
#pragma unroll
        for (int ni = 0; ni < 4; ni++) {
            int col = n_w + ni * 8 + (lane & 3) * 2;
            float v0 = acc[mi][ni][0], v1 = acc[mi][ni][1];
            float v2 = acc[mi][ni][2], v3 = acc[mi][ni][3];
            if (EPI == 3) {
                float b0 = bias[col], b1 = bias[col + 1];
                *(float2*)(Cf + (long)b * cStr + (long)r0 * 128 + col) = make_float2(v0 + b0, v1 + b1);
                *(float2*)(Cf + (long)b * cStr + (long)r1 * 128 + col) = make_float2(v2 + b0, v3 + b1);
            } else if (EPI == 1 || EPI == 4) {
                if (EPI == 1) {
                    v0 = silu(v0 * rs0); v1 = silu(v1 * rs0);
                    v2 = silu(v2 * rs1); v3 = silu(v3 * rs1);
                } else {
                    v0 *= w[mi * 2 + 0][ni * 2 + 0];
                    v1 *= w[mi * 2 + 0][ni * 2 + 1];
                    v2 *= w[mi * 2 + 1][ni * 2 + 0];
                    v3 *= w[mi * 2 + 1][ni * 2 + 1];
                }
                __nv_bfloat16 h, l;
                __nv_bfloat162 h01, l01, h23, l23;
                split2(v0, h, l); h01.x = h; l01.x = l;
                split2(v1, h, l); h01.y = h; l01.y = l;
                split2(v2, h, l); h23.x = h; l23.x = l;
                split2(v3, h, l); h23.y = h; l23.y = l;
                long o0 = (long)b * cStr + (long)r0 * 128 + col;
                long o1 = (long)b * cStr + (long)r1 * 128 + col;
                *(__nv_bfloat162*)(Ch + o0) = h01;
                *(__nv_bfloat162*)(Cl + o0) = l01;
                *(__nv_bfloat162*)(Ch + o1) = h23;
                *(__nv_bfloat162*)(Cl + o1) = l23;
            } else {  // EPI == 2 gated
                float bx = bias[n0 + col], bz = bias[n0 + col + 1];
                float u0 = (v0 + bx) * silu(v1 + bz) * rs0;
                float u1 = (v2 + bx) * silu(v3 + bz) * rs1;
                int dcol = blockIdx.z * 64 + (col >> 1);
                __nv_bfloat16 h0, l0, h1, l1;
                split2(u0, h0, l0);
                split2(u1, h1, l1);
                long o0 = (long)b * cStr + (long)r0 * 128 + dcol;
                long o1 = (long)b * cStr + (long)r1 * 128 + dcol;
                Ch[o0] = h0; Cl[o0] = l0;
                Ch[o1] = h1; Cl[o1] = l1;
            }
        }
    }
}

// ---------------- launch ----------------------------------------------------
extern "C" void kernel_launch(void* const* d_in, const int* in_sizes, int n_in,
                              void* d_out, int out_size)
{
    const float* x        = (const float*)d_in[0];
    const float* EigVecs  = (const float*)d_in[2];
    const float* EigVals  = (const float*)d_in[3];
    const float* bn_gamma = (const float*)d_in[4];
    const float* bn_beta  = (const float*)d_in[5];
    const float* bn_mean  = (const float*)d_in[6];
    const float* bn_var   = (const float*)d_in[7];
    const float* W_in     = (const float*)d_in[8];
    const float* b_in     = (const float*)d_in[9];
    const float* log_Delta= (const float*)d_in[10];
    const float* Bp       = (const float*)d_in[11];
    const float* Cp       = (const float*)d_in[12];
    const float* log_A    = (const float*)d_in[13];
    const float* A_imag   = (const float*)d_in[14];
    const float* W_out    = (const float*)d_in[15];
    const float* b_out    = (const float*)d_in[16];
    float* y = (float*)d_out;

    float *p_rinv, *p_bp;
    __nv_bfloat16 *p_Eh, *p_El, *p_xh, *p_xl, *p_uh, *p_ul, *p_Gh, *p_Gl, *p_vh, *p_vl;
    __nv_bfloat16 *p_Wih, *p_Wil, *p_Woh, *p_Wol;
    cudaGetSymbolAddress((void**)&p_rinv, g_rinv);
    cudaGetSymbolAddress((void**)&p_bp, g_bp);
    cudaGetSymbolAddress((void**)&p_Eh, g_Eh);
    cudaGetSymbolAddress((void**)&p_El, g_El);
    cudaGetSymbolAddress((void**)&p_xh, g_xh);
    cudaGetSymbolAddress((void**)&p_xl, g_xl);
    cudaGetSymbolAddress((void**)&p_uh, g_uh);
    cudaGetSymbolAddress((void**)&p_ul, g_ul);
    cudaGetSymbolAddress((void**)&p_Gh, g_Gh);
    cudaGetSymbolAddress((void**)&p_Gl, g_Gl);
    cudaGetSymbolAddress((void**)&p_vh, g_vh);
    cudaGetSymbolAddress((void**)&p_vl, g_vl);
    cudaGetSymbolAddress((void**)&p_Wih, g_Wih);
    cudaGetSymbolAddress((void**)&p_Wil, g_Wil);
    cudaGetSymbolAddress((void**)&p_Woh, g_Woh);
    cudaGetSymbolAddress((void**)&p_Wol, g_Wol);

    const int SMEM = 4 * (2 * (32 * 80) + 2 * (32 * 272));   // 90112
    cudaFuncSetAttribute(mma_gemm<false, 2>, cudaFuncAttributeMaxDynamicSharedMemorySize, SMEM);
    cudaFuncSetAttribute(mma_gemm<true, 4>,  cudaFuncAttributeMaxDynamicSharedMemorySize, SMEM);
    cudaFuncSetAttribute(mma_gemm<false, 1>, cudaFuncAttributeMaxDynamicSharedMemorySize, SMEM);
    cudaFuncSetAttribute(mma_gemm<false, 3>, cudaFuncAttributeMaxDynamicSharedMemorySize, SMEM);

    const long M128 = (long)L_ * D_;        // 131072
    const long M1M  = (long)L_ * KE;        // 1048576

    // 1) tables + weight prep
    k_prep<<<202, 256>>>(bn_gamma, bn_beta, bn_mean, bn_var, log_Delta, Bp, Cp,
                         log_A, A_imag, W_in, b_in, W_out);
    // 2) fused rinv + E split
    k_erow<<<B_ * L_ / 8, 256>>>(EigVecs);
    // 3) x -> bn(x) bf16 split
    k_xcvt<<<(int)((long)B_ * L_ * D_ / 4 / 256), 256>>>(x);
    // 4) in-proj + gated act fused: u' (bf16 hi/lo)
    mma_gemm<false, 2><<<dim3(32, 8, 2), 128, SMEM>>>(
        p_xh, p_xl, p_Wih, p_Wil, nullptr, p_uh, p_ul, p_rinv, p_bp,
        4, 128, 256, M128, 0, M128);
    // 5) G[b][k][d] = (sum_l E[l][k] * u'[l][d]) * W(b,k,d)   (k_w fused in epilogue)
    mma_gemm<true, 4><<<dim3(32, 8, 1), 128, SMEM>>>(
        p_Eh, p_El, p_uh, p_ul, nullptr, p_Gh, p_Gl, nullptr, EigVals,
        32, 1024, 128, M1M, M128, M128);
    // 6) v = silu(rinv * E @ G) -> bf16 hi/lo
    mma_gemm<false, 1><<<dim3(32, 8, 1), 128, SMEM>>>(
        p_Eh, p_El, p_Gh, p_Gl, nullptr, p_vh, p_vl, p_rinv, nullptr,
        32, 1024, 128, M1M, M128, M128);
    // 7) y = v @ W_out + b_out
    mma_gemm<false, 3><<<dim3(32, 8, 1), 128, SMEM>>>(
        p_vh, p_vl, p_Woh, p_Wol, y, nullptr, nullptr, nullptr, b_out,
        4, 128, 128, M128, 0, M128);
}

// round 12
// speedup vs baseline: 2.1490x; 1.0194x over previous
#include <cuda_runtime.h>
#include <cuda_bf16.h>
#include <math.h>
#include <stdint.h>

// Problem constants
static constexpr int B_ = 8;
static constexpr int L_ = 1024;
static constexpr int KE = 1024;
static constexpr int D_ = 128;
static constexpr int S_ = 16;

// ---------------- scratch (device globals) ----------------------------------
__device__ float g_rinv[B_ * L_];
__device__ __nv_bfloat16 g_Eh[(long)B_ * L_ * KE];
__device__ __nv_bfloat16 g_El[(long)B_ * L_ * KE];
__device__ __nv_bfloat16 g_xh[(long)B_ * L_ * D_];   // bn(x) hi/lo
__device__ __nv_bfloat16 g_xl[(long)B_ * L_ * D_];
__device__ __nv_bfloat16 g_uh[(long)B_ * L_ * D_];   // u' = x1*silu(z)*rinv
__device__ __nv_bfloat16 g_ul[(long)B_ * L_ * D_];
__device__ __nv_bfloat16 g_Gh[(long)B_ * KE * D_];   // G = QTX * W
__device__ __nv_bfloat16 g_Gl[(long)B_ * KE * D_];
__device__ __nv_bfloat16 g_vh[(long)B_ * L_ * D_];   // silu(yssm)
__device__ __nv_bfloat16 g_vl[(long)B_ * L_ * D_];
__device__ __nv_bfloat16 g_Wih[D_ * 2 * D_];         // W_in packed (x1,z interleaved)
__device__ __nv_bfloat16 g_Wil[D_ * 2 * D_];
__device__ __nv_bfloat16 g_Woh[D_ * D_];
__device__ __nv_bfloat16 g_Wol[D_ * D_];
__device__ float g_bp[2 * D_];                       // b_in packed
__device__ float g_ar[D_ * S_];                      // Re(Abar)
__device__ float g_m2[D_ * S_];                      // |Abar|^2
__device__ float g_bc[D_ * S_];                      // delta*Bp*Cp
__device__ float g_bns[D_];
__device__ float g_bnb[D_];

// ---------------- helpers ----------------------------------------------------
__device__ __forceinline__ uint32_t smem_u32(const void* p) {
    uint32_t a;
    asm("{ .reg .u64 t; cvta.to.shared.u64 t, %1; cvt.u32.u64 %0, t; }" : "=r"(a) : "l"(p));
    return a;
}
__device__ __forceinline__ void split2(float x, __nv_bfloat16& h, __nv_bfloat16& l) {
    h = __float2bfloat16_rn(x);
    l = __float2bfloat16_rn(x - __bfloat162float(h));
}

#define CP16(dst, src) \
    asm volatile("cp.async.ca.shared.global [%0], [%1], 16;" :: "r"(dst), "l"(src))
#define CP_COMMIT() asm volatile("cp.async.commit_group;" ::: "memory")
#define CP_WAIT(n)  asm volatile("cp.async.wait_group %0;" :: "n"(n) : "memory")

__device__ __forceinline__ void ldm_x4(uint32_t* r, uint32_t a) {
    asm volatile("ldmatrix.sync.aligned.m8n8.x4.shared.b16 {%0,%1,%2,%3}, [%4];"
        : "=r"(r[0]), "=r"(r[1]), "=r"(r[2]), "=r"(r[3]) : "r"(a));
}
__device__ __forceinline__ void ldm_x4t(uint32_t* r, uint32_t a) {
    asm volatile("ldmatrix.sync.aligned.m8n8.x4.trans.shared.b16 {%0,%1,%2,%3}, [%4];"
        : "=r"(r[0]), "=r"(r[1]), "=r"(r[2]), "=r"(r[3]) : "r"(a));
}
__device__ __forceinline__ void mma_bf16(float* c, const uint32_t* a, uint32_t b0, uint32_t b1) {
    asm volatile("mma.sync.aligned.m16n8k16.row.col.f32.bf16.bf16.f32 "
        "{%0,%1,%2,%3}, {%4,%5,%6,%7}, {%8,%9}, {%0,%1,%2,%3};"
        : "+f"(c[0]), "+f"(c[1]), "+f"(c[2]), "+f"(c[3])
        : "r"(a[0]), "r"(a[1]), "r"(a[2]), "r"(a[3]), "r"(b0), "r"(b1));
}
__device__ __forceinline__ float silu(float v) { return v / (1.f + expf(-v)); }
__device__ __forceinline__ uint32_t bf2u(__nv_bfloat162 v) { return *(uint32_t*)&v; }

// ---------------- merged prep: E split+rinv | x split | tables ---------------
// blocks [0,1024)        : E rows (8 rows per block)
// blocks [1024,2048)     : x -> bn(x) hi/lo
// blocks [2048,2250)     : SSM tables + BN fold + weight pack/split
__global__ __launch_bounds__(256)
void k_all_prep(const float* __restrict__ E, const float* __restrict__ x,
                const float* __restrict__ gamma, const float* __restrict__ beta,
                const float* __restrict__ mean,  const float* __restrict__ var,
                const float* __restrict__ log_Delta,
                const float* __restrict__ Bp,    const float* __restrict__ Cp,
                const float* __restrict__ log_A_real,
                const float* __restrict__ A_imag,
                const float* __restrict__ W_in,  const float* __restrict__ b_in,
                const float* __restrict__ W_out)
{
    int blk = blockIdx.x;
    if (blk < 1024) {
        // ---- E rows: inv-norm + bf16 hi/lo split ----
        int row = blk * 8 + (threadIdx.x >> 5);
        int lane = threadIdx.x & 31;
        const float4* p = (const float4*)(E + (long)row * KE);
        uint2* oh = (uint2*)(g_Eh + (long)row * KE);
        uint2* ol = (uint2*)(g_El + (long)row * KE);
        float s = 0.f;
#pragma unroll
        for (int i = 0; i < 8; i++) {
            int c4 = lane + i * 32;
            float4 v = p[c4];
            s += v.x * v.x + v.y * v.y + v.z * v.z + v.w * v.w;
            __nv_bfloat162 h01, h23, l01, l23;
            h01.x = __float2bfloat16_rn(v.x); l01.x = __float2bfloat16_rn(v.x - __bfloat162float(h01.x));
            h01.y = __float2bfloat16_rn(v.y); l01.y = __float2bfloat16_rn(v.y - __bfloat162float(h01.y));
            h23.x = __float2bfloat16_rn(v.z); l23.x = __float2bfloat16_rn(v.z - __bfloat162float(h23.x));
            h23.y = __float2bfloat16_rn(v.w); l23.y = __float2bfloat16_rn(v.w - __bfloat162float(h23.y));
            oh[c4] = make_uint2(bf2u(h01), bf2u(h23));
            ol[c4] = make_uint2(bf2u(l01), bf2u(l23));
        }
#pragma unroll
        for (int o = 16; o; o >>= 1) s += __shfl_xor_sync(0xffffffffu, s, o);
        if (lane == 0) g_rinv[row] = (s > 0.f) ? (1.0f / sqrtf(s)) : 0.f;
    } else if (blk < 2048) {
        // ---- x -> bn(x) bf16 hi/lo ----
        long i = (long)(blk - 1024) * 256 + threadIdx.x;   // float4 index
        int c = ((int)i & 31) * 4;
        float4 v = ((const float4*)x)[i];
        v.x = v.x * g_bns[c + 0] + g_bnb[c + 0];   // NOTE: g_bns written by table blocks
        // (safe: see barrier-free note below — tables written before use via separate pass)
        v.y = v.y * g_bns[c + 1] + g_bnb[c + 1];
        v.z = v.z * g_bns[c + 2] + g_bnb[c + 2];
        v.w = v.w * g_bns[c + 3] + g_bnb[c + 3];
        __nv_bfloat162 h01, h23, l01, l23;
        h01.x = __float2bfloat16_rn(v.x); l01.x = __float2bfloat16_rn(v.x - __bfloat162float(h01.x));
        h01.y = __float2bfloat16_rn(v.y); l01.y = __float2bfloat16_rn(v.y - __bfloat162float(h01.y));
        h23.x = __float2bfloat16_rn(v.z); l23.x = __float2bfloat16_rn(v.z - __bfloat162float(h23.x));
        h23.y = __float2bfloat16_rn(v.w); l23.y = __float2bfloat16_rn(v.w - __bfloat162float(h23.y));
        ((uint2*)g_xh)[i] = make_uint2(bf2u(h01), bf2u(h23));
        ((uint2*)g_xl)[i] = make_uint2(bf2u(l01), bf2u(l23));
    } else {
        // ---- tables + weight pack/split ----
        int idx = (blk - 2048) * 256 + threadIdx.x;
        if (idx < 2048) {
            int d = idx / S_;
            float delta = expf(log_Delta[d]);
            float aRe = -expf(log_A_real[idx]);
            float aIm = A_imag[idx];
            float mag = expf(-1e-3f + delta * aRe);
            float sn, cs;
            sincosf(delta * aIm, &sn, &cs);
            float ar = mag * cs, ai = mag * sn;
            g_ar[idx] = ar;
            g_m2[idx] = ar * ar + ai * ai;
            g_bc[idx] = delta * Bp[idx] * Cp[idx];
        } else if (idx < 2048 + 32768) {   // W_in pack + split
            int j = idx - 2048;
            int c = j >> 8, n = j & 255;
            int d = n >> 1, half = n & 1;
            float w = W_in[c * 256 + half * 128 + d];
            __nv_bfloat16 h, l;
            split2(w, h, l);
            g_Wih[j] = h; g_Wil[j] = l;
        } else if (idx < 2048 + 32768 + 16384) {  // W_out split
            int j = idx - (2048 + 32768);
            float w = W_out[j];
            __nv_bfloat16 h, l;
            split2(w, h, l);
            g_Woh[j] = h; g_Wol[j] = l;
        } else if (idx < 2048 + 32768 + 16384 + 256) {  // bias pack
            int j = idx - (2048 + 32768 + 16384);
            g_bp[j] = b_in[(j & 1) * 128 + (j >> 1)];
        }
    }
}

// BN fold must complete BEFORE the x-split blocks read g_bns/g_bnb, so it runs
// in a tiny separate kernel launched first (no cross-block ordering inside one grid).
__global__ void k_bn(const float* __restrict__ gamma, const float* __restrict__ beta,
                     const float* __restrict__ mean,  const float* __restrict__ var)
{
    int d = threadIdx.x;
    float sc = gamma[d] * rsqrtf(var[d] + 1e-5f);
    g_bns[d] = sc;
    g_bnb[d] = beta[d] - mean[d] * sc;
}

// ---------------- split-bf16 HMMA GEMM, 32x128 tile, 4 warps, NST stages -----
// Per batch b (blockIdx.y): C[m][n] = sum_c opA[m][c] * B[c][n]
// EPI 1: silu(rinv*acc)->bf16 hi/lo | EPI 2: gated pair -> bf16 hi/lo
// EPI 3: acc + bias -> fp32        | EPI 4: fused SSM weight -> bf16 hi/lo (G)
//   (EPI 4: `bias` carries EigVals)
template <bool TRANSA, int EPI, int NST>
__global__ __launch_bounds__(128)
void mma_gemm(const __nv_bfloat16* __restrict__ Ah, const __nv_bfloat16* __restrict__ Al,
              const __nv_bfloat16* __restrict__ Bh, const __nv_bfloat16* __restrict__ Bl,
              float* __restrict__ Cf, __nv_bfloat16* __restrict__ Ch, __nv_bfloat16* __restrict__ Cl,
              const float* __restrict__ rinv, const float* __restrict__ bias,
              int nch, int lda, int ldb, long aStr, long bStr, long cStr)
{
    constexpr int A_SZ  = 32 * 80;        // 32 rows x (64B data + 16B pad)
    constexpr int ASTRB = 80;
    constexpr int B_SZ  = 32 * 272;       // 32 rows x (256B data + 16B pad)
    constexpr int BSTRB = 272;
    constexpr int STAGE = 2 * A_SZ + 2 * B_SZ;   // 22528

    extern __shared__ char smem[];
    const uint32_t sb = smem_u32(smem);

    const int tid  = threadIdx.x;
    const int lane = tid & 31;
    const int wid  = tid >> 5;
    const int n_w  = wid * 32;
    const int b    = blockIdx.y;
    const int m0   = blockIdx.x * 32;
    const int n0   = blockIdx.z * 128;

    const int arow = tid >> 2;      // 0..31
    const int acol = tid & 3;       // 16B col

    float acc[2][4][4];
#pragma unroll
    for (int i = 0; i < 2; i++)
#pragma unroll
        for (int j = 0; j < 4; j++)
#pragma unroll
            for (int q = 0; q < 4; q++) acc[i][j][q] = 0.f;

    auto issue_chunk = [&](int ch) {
        const uint32_t st = sb + (uint32_t)(ch % NST) * STAGE;
        long g;
        if (TRANSA) g = (long)b * aStr + (long)(ch * 32 + arow) * lda + m0 + acol * 8;
        else        g = (long)b * aStr + (long)(m0 + arow) * lda + ch * 32 + acol * 8;
        uint32_t dst = st + arow * ASTRB + acol * 16;
        CP16(dst,        Ah + g);
        CP16(dst + A_SZ, Al + g);
#pragma unroll
        for (int q = 0; q < 4; q++) {
            int idx = tid + q * 128;
            int row = idx >> 4, c4 = idx & 15;
            long gb = (long)b * bStr + (long)(ch * 32 + row) * ldb + n0 + c4 * 8;
            uint32_t d2 = st + 2 * A_SZ + row * BSTRB + c4 * 16;
            CP16(d2,        Bh + gb);
            CP16(d2 + B_SZ, Bl + gb);
        }
        CP_COMMIT();
    };

#pragma unroll
    for (int i = 0; i < NST - 1; i++) issue_chunk(i);

    for (int ch = 0; ch < nch; ++ch) {
        CP_WAIT(NST - 2);
        __syncthreads();
        if (ch + NST - 1 < nch) issue_chunk(ch + NST - 1);
        else                    CP_COMMIT();

        const uint32_t st = sb + (uint32_t)(ch % NST) * STAGE;
        const uint32_t aOff = st;
        const uint32_t bOff = st + 2 * A_SZ;

        uint32_t ah[2][2][4], al[2][2][4];
#pragma unroll
        for (int mi = 0; mi < 2; mi++)
#pragma unroll
            for (int kk = 0; kk < 2; kk++) {
                uint32_t addr;
                if (TRANSA) {
                    int g = lane >> 3, r = lane & 7;
                    int row = kk * 16 + ((g & 2) ? 8 : 0) + r;
                    int col = mi * 16 + ((g & 1) ? 8 : 0);
                    addr = aOff + row * ASTRB + col * 2;
                    ldm_x4t(ah[mi][kk], addr);
                    ldm_x4t(al[mi][kk], addr + A_SZ);
                } else {
                    int row = mi * 16 + (lane & 15);
                    int col = kk * 16 + (lane >> 4) * 8;
                    addr = aOff + row * ASTRB + col * 2;
                    ldm_x4(ah[mi][kk], addr);
                    ldm_x4(al[mi][kk], addr + A_SZ);
                }
            }
        uint32_t bh[2][2][4], bl[2][2][4];
#pragma unroll
        for (int bi = 0; bi < 2; bi++)
#pragma unroll
            for (int kk = 0; kk < 2; kk++) {
                int g = lane >> 3, r = lane & 7;
                int row = kk * 16 + ((g & 2) ? 8 : 0) + r;
                int col = n_w + bi * 16 + ((g & 1) ? 8 : 0);
                uint32_t addr = bOff + row * BSTRB + col * 2;
                ldm_x4t(bh[bi][kk], addr);
                ldm_x4t(bl[bi][kk], addr + B_SZ);
            }

#pragma unroll
        for (int mi = 0; mi < 2; mi++)
#pragma unroll
            for (int bi = 0; bi < 2; bi++)
#pragma unroll
                for (int sub = 0; sub < 2; sub++) {
                    float* c = acc[mi][bi * 2 + sub];
#pragma unroll
                    for (int kk = 0; kk < 2; kk++) {
                        uint32_t bh0 = bh[bi][kk][sub], bh1 = bh[bi][kk][sub + 2];
                        uint32_t bl0 = bl[bi][kk][sub], bl1 = bl[bi][kk][sub + 2];
                        mma_bf16(c, ah[mi][kk], bh0, bh1);
                        mma_bf16(c, al[mi][kk], bh0, bh1);
                        mma_bf16(c, ah[mi][kk], bl0, bl1);
                    }
                }
    }

    // ---- fused SSM weights (EPI 4): w[e-row][d-col], tables read once -------
    float w[4][8];
    if (EPI == 4) {
        float ee[4], ee2[4];
#pragma unroll
        for (int mi = 0; mi < 2; mi++) {
            int r = m0 + mi * 16 + (lane >> 2);
            ee[mi * 2 + 0] = 1.0f - bias[b * 1024 + r];
            ee[mi * 2 + 1] = 1.0f - bias[b * 1024 + r + 8];
        }
#pragma unroll
        for (int q = 0; q < 4; q++) ee2[q] = ee[q] * ee[q];
#pragma unroll
        for (int j = 0; j < 8; j++) {
            int d = n_w + (j >> 1) * 8 + (lane & 3) * 2 + (j & 1);
            const float* par = g_ar + d * S_;
            const float* pm2 = g_m2 + d * S_;
            const float* pbc = g_bc + d * S_;
            float w0 = 0.f, w1 = 0.f, w2 = 0.f, w3 = 0.f;
#pragma unroll
            for (int s = 0; s < S_; s++) {
                float ar = par[s], m2 = pm2[s], bc = pbc[s];
                float t1, t2;
                t1 = ee[0] * ar; t2 = ee2[0] * m2;
                w0 += __fdividef(t1 - t2, 1.f - 2.f * t1 + t2) * bc;
                t1 = ee[1] * ar; t2 = ee2[1] * m2;
                w1 += __fdividef(t1 - t2, 1.f - 2.f * t1 + t2) * bc;
                t1 = ee[2] * ar; t2 = ee2[2] * m2;
                w2 += __fdividef(t1 - t2, 1.f - 2.f * t1 + t2) * bc;
                t1 = ee[3] * ar; t2 = ee2[3] * m2;
                w3 += __fdividef(t1 - t2, 1.f - 2.f * t1 + t2) * bc;
            }
            w[0][j] = w0; w[1][j] = w1; w[2][j] = w2; w[3][j] = w3;
        }
    }

    // ---- epilogue ----
#pragma unroll
    for (int mi = 0; mi < 2; mi++) {
        int r0 = m0 + mi * 16 + (lane >> 2);
        int r1 = r0 + 8;
        float rs0 = 1.f, rs1 = 1.f;
        if (EPI == 1 || EPI == 2) {
            rs0 = rinv[b * 1024 + r0];
            rs1 = rinv[b * 1024 + r1];
        }
#pragma unroll
        for (int ni = 0; ni < 4; ni++) {
            int col = n_w + ni * 8 + (lane & 3) * 2;
            float v0 = acc[mi][ni][0], v1 = acc[mi][ni][1];
            float v2 = acc[mi][ni][2], v3 = acc[mi][ni][3];
            if (EPI == 3) {
                float b0 = bias[col], b1 = bias[col + 1];
                *(float2*)(Cf + (long)b * cStr + (long)r0 * 128 + col) = make_float2(v0 + b0, v1 + b1);
                *(float2*)(Cf + (long)b * cStr + (long)r1 * 128 + col) = make_float2(v2 + b0, v3 + b1);
            } else if (EPI == 1 || EPI == 4) {
                if (EPI == 1) {
                    v0 = silu(v0 * rs0); v1 = silu(v1 * rs0);
                    v2 = silu(v2 * rs1); v3 = silu(v3 * rs1);
                } else {
                    v0 *= w[mi * 2 + 0][ni * 2 + 0];
                    v1 *= w[mi * 2 + 0][ni * 2 + 1];
                    v2 *= w[mi * 2 + 1][ni * 2 + 0];
                    v3 *= w[mi * 2 + 1][ni * 2 + 1];
                }
                __nv_bfloat16 h, l;
                __nv_bfloat162 h01, l01, h23, l23;
                split2(v0, h, l); h01.x = h; l01.x = l;
                split2(v1, h, l); h01.y = h; l01.y = l;
                split2(v2, h, l); h23.x = h; l23.x = l;
                split2(v3, h, l); h23.y = h; l23.y = l;
                long o0 = (long)b * cStr + (long)r0 * 128 + col;
                long o1 = (long)b * cStr + (long)r1 * 128 + col;
                *(__nv_bfloat162*)(Ch + o0) = h01;
                *(__nv_bfloat162*)(Cl + o0) = l01;
                *(__nv_bfloat162*)(Ch + o1) = h23;
                *(__nv_bfloat162*)(Cl + o1) = l23;
            } else {  // EPI == 2 gated
                float bx = bias[n0 + col], bz = bias[n0 + col + 1];
                float u0 = (v0 + bx) * silu(v1 + bz) * rs0;
                float u1 = (v2 + bx) * silu(v3 + bz) * rs1;
                int dcol = blockIdx.z * 64 + (col >> 1);
                __nv_bfloat16 h0, l0, h1, l1;
                split2(u0, h0, l0);
                split2(u1, h1, l1);
                long o0 = (long)b * cStr + (long)r0 * 128 + dcol;
                long o1 = (long)b * cStr + (long)r1 * 128 + dcol;
                Ch[o0] = h0; Cl[o0] = l0;
                Ch[o1] = h1; Cl[o1] = l1;
            }
        }
    }
}

// ---------------- launch ----------------------------------------------------
extern "C" void kernel_launch(void* const* d_in, const int* in_sizes, int n_in,
                              void* d_out, int out_size)
{
    const float* x        = (const float*)d_in[0];
    const float* EigVecs  = (const float*)d_in[2];
    const float* EigVals  = (const float*)d_in[3];
    const float* bn_gamma = (const float*)d_in[4];
    const float* bn_beta  = (const float*)d_in[5];
    const float* bn_mean  = (const float*)d_in[6];
    const float* bn_var   = (const float*)d_in[7];
    const float* W_in     = (const float*)d_in[8];
    const float* b_in     = (const float*)d_in[9];
    const float* log_Delta= (const float*)d_in[10];
    const float* Bp       = (const float*)d_in[11];
    const float* Cp       = (const float*)d_in[12];
    const float* log_A    = (const float*)d_in[13];
    const float* A_imag   = (const float*)d_in[14];
    const float* W_out    = (const float*)d_in[15];
    const float* b_out    = (const float*)d_in[16];
    float* y = (float*)d_out;

    float *p_rinv, *p_bp;
    __nv_bfloat16 *p_Eh, *p_El, *p_xh, *p_xl, *p_uh, *p_ul, *p_Gh, *p_Gl, *p_vh, *p_vl;
    __nv_bfloat16 *p_Wih, *p_Wil, *p_Woh, *p_Wol;
    cudaGetSymbolAddress((void**)&p_rinv, g_rinv);
    cudaGetSymbolAddress((void**)&p_bp, g_bp);
    cudaGetSymbolAddress((void**)&p_Eh, g_Eh);
    cudaGetSymbolAddress((void**)&p_El, g_El);
    cudaGetSymbolAddress((void**)&p_xh, g_xh);
    cudaGetSymbolAddress((void**)&p_xl, g_xl);
    cudaGetSymbolAddress((void**)&p_uh, g_uh);
    cudaGetSymbolAddress((void**)&p_ul, g_ul);
    cudaGetSymbolAddress((void**)&p_Gh, g_Gh);
    cudaGetSymbolAddress((void**)&p_Gl, g_Gl);
    cudaGetSymbolAddress((void**)&p_vh, g_vh);
    cudaGetSymbolAddress((void**)&p_vl, g_vl);
    cudaGetSymbolAddress((void**)&p_Wih, g_Wih);
    cudaGetSymbolAddress((void**)&p_Wil, g_Wil);
    cudaGetSymbolAddress((void**)&p_Woh, g_Woh);
    cudaGetSymbolAddress((void**)&p_Wol, g_Wol);

    const int SMEM4 = 4 * 22528;   // 90112  (big GEMMs)
    const int SMEM3 = 3 * 22528;   // 67584  (small GEMMs)
    cudaFuncSetAttribute(mma_gemm<false, 2, 3>, cudaFuncAttributeMaxDynamicSharedMemorySize, SMEM3);
    cudaFuncSetAttribute(mma_gemm<true, 4, 4>,  cudaFuncAttributeMaxDynamicSharedMemorySize, SMEM4);
    cudaFuncSetAttribute(mma_gemm<false, 1, 4>, cudaFuncAttributeMaxDynamicSharedMemorySize, SMEM4);
    cudaFuncSetAttribute(mma_gemm<false, 3, 3>, cudaFuncAttributeMaxDynamicSharedMemorySize, SMEM3);

    const long M128 = (long)L_ * D_;        // 131072
    const long M1M  = (long)L_ * KE;        // 1048576

    // 1) BN fold (must precede merged prep's x-split blocks)
    k_bn<<<1, 128>>>(bn_gamma, bn_beta, bn_mean, bn_var);
    // 2) merged prep: E split+rinv | x split | tables+weights  (one launch)
    k_all_prep<<<2250, 256>>>(EigVecs, x, bn_gamma, bn_beta, bn_mean, bn_var,
                              log_Delta, Bp, Cp, log_A, A_imag, W_in, b_in, W_out);
    // 3) in-proj + gated act fused: u' (bf16 hi/lo)
    mma_gemm<false, 2, 3><<<dim3(32, 8, 2), 128, SMEM3>>>(
        p_xh, p_xl, p_Wih, p_Wil, nullptr, p_uh, p_ul, p_rinv, p_bp,
        4, 128, 256, M128, 0, M128);
    // 4) G[b][k][d] = (sum_l E[l][k] * u'[l][d]) * W(b,k,d)
    mma_gemm<true, 4, 4><<<dim3(32, 8, 1), 128, SMEM4>>>(
        p_Eh, p_El, p_uh, p_ul, nullptr, p_Gh, p_Gl, nullptr, EigVals,
        32, 1024, 128, M1M, M128, M128);
    // 5) v = silu(rinv * E @ G) -> bf16 hi/lo
    mma_gemm<false, 1, 4><<<dim3(32, 8, 1), 128, SMEM4>>>(
        p_Eh, p_El, p_Gh, p_Gl, nullptr, p_vh, p_vl, p_rinv, nullptr,
        32, 1024, 128, M1M, M128, M128);
    // 6) y = v @ W_out + b_out
    mma_gemm<false, 3, 3><<<dim3(32, 8, 1), 128, SMEM3>>>(
        p_vh, p_vl, p_Woh, p_Wol, y, nullptr, nullptr, nullptr, b_out,
        4, 128, 128, M128, 0, M128);
}